// round 12
// baseline (speedup 1.0000x reference)
#include <cuda_runtime.h>
#include <cuda_bf16.h>
#include <math.h>

// ---------------------------------------------------------------------------
// AGCRN cell, B=64, N=2048, Din=2, H=64, K=3, D=16.
// R8: GEMMs on mma.sync bf16x3 (unchanged). Projection rewritten: 4 nodes per
// block (W L2 traffic /4), k-tiled smem staging, FFMA2 micro-GEMM.
// ---------------------------------------------------------------------------

#define Nn 2048
#define Bb 64
#define Cc 66
#define BC 4224             // Bb * Cc = 33 * 128
#define KC 198              // 3 * Cc
#define OG 128
#define OU 64
#define Hh 64

#define MT 128              // GEMM m-tile (nodes)
#define NT 128              // GEMM n-tile (bc columns)
#define KT 32               // k per stage
#define NKC (Nn / KT)       // 64 stages
#define PL 10240            // bytes per smem plane: 128 rows * 80B
#define STG (4 * PL)        // 40960 bytes per pipeline stage

#define NPB 4               // proj: nodes per block
#define TKI 33              // proj: k-tile
#define NTL 6               // proj: number of k-tiles (6*33 = 198)

// scratch (__device__ globals)
__device__ __nv_bfloat16 g_Shi[(size_t)Nn * Nn];   // S hi plane (k-major rows)
__device__ __nv_bfloat16 g_Slo[(size_t)Nn * Nn];
__device__ __nv_bfloat16 g_Xth[(size_t)BC * Nn];   // X^T hi (bc-major rows)
__device__ __nv_bfloat16 g_Xtl[(size_t)BC * Nn];
__device__ __nv_bfloat16 g_Yth[(size_t)BC * Nn];   // Y1^T hi
__device__ __nv_bfloat16 g_Ytl[(size_t)BC * Nn];
__device__ float g_X0[(size_t)Nn * BC];            // node-major fp32
__device__ float g_Y1[(size_t)Nn * BC];
__device__ float g_Y2[(size_t)Nn * BC];
__device__ float g_ZR[(size_t)Bb * Nn * OG];       // gate out, [b][n][2H]

// ---------------------------------------------------------------------------
// PTX helpers (plain-sm_103-legal)
// ---------------------------------------------------------------------------
__device__ __forceinline__ unsigned smem_u32(const void* p) {
    unsigned a;
    asm("{ .reg .u64 t; cvta.to.shared.u64 t, %1; cvt.u32.u64 %0, t; }" : "=r"(a) : "l"(p));
    return a;
}
__device__ __forceinline__ void cpa16(unsigned dst, const void* src) {
    asm volatile("cp.async.cg.shared.global [%0], [%1], 16;" :: "r"(dst), "l"(src));
}
__device__ __forceinline__ void ldsm4(unsigned* r, unsigned a) {
    asm volatile("ldmatrix.sync.aligned.m8n8.x4.shared.b16 {%0,%1,%2,%3}, [%4];"
                 : "=r"(r[0]), "=r"(r[1]), "=r"(r[2]), "=r"(r[3]) : "r"(a));
}
__device__ __forceinline__ void mma_bf16(float* c, const unsigned* a, const unsigned* b) {
    asm volatile(
        "mma.sync.aligned.m16n8k16.row.col.f32.bf16.bf16.f32 "
        "{%0,%1,%2,%3}, {%4,%5,%6,%7}, {%8,%9}, {%0,%1,%2,%3};"
        : "+f"(c[0]), "+f"(c[1]), "+f"(c[2]), "+f"(c[3])
        : "r"(a[0]), "r"(a[1]), "r"(a[2]), "r"(a[3]), "r"(b[0]), "r"(b[1]));
}
__device__ __forceinline__ void ffma2(unsigned long long& d, unsigned long long a,
                                      unsigned long long b) {
    asm("fma.rn.f32x2 %0, %1, %2, %0;" : "+l"(d) : "l"(a), "l"(b));
}
__device__ __forceinline__ unsigned long long dup2(float v) {
    unsigned long long r;
    unsigned u = __float_as_uint(v);
    asm("mov.b64 %0, {%1, %1};" : "=l"(r) : "r"(u));
    return r;
}
__device__ __forceinline__ unsigned long long packf2(float x, float y) {
    unsigned long long r;
    asm("mov.b64 %0, {%1, %2};" : "=l"(r) : "r"(__float_as_uint(x)), "r"(__float_as_uint(y)));
    return r;
}
union F2u { unsigned long long u; float2 f; };

// ---------------------------------------------------------------------------
// K1: supports (one block per row n)  -> bf16 hi/lo planes of S
// ---------------------------------------------------------------------------
__device__ __forceinline__ float block_reduce(float v, float* red, int tid, bool ismax) {
    red[tid] = v;
    __syncthreads();
    for (int s = 128; s > 0; s >>= 1) {
        if (tid < s) red[tid] = ismax ? fmaxf(red[tid], red[tid + s]) : (red[tid] + red[tid + s]);
        __syncthreads();
    }
    float r = red[0];
    __syncthreads();
    return r;
}

__global__ void __launch_bounds__(256) supports_kernel(const float* __restrict__ E,
                                                       const float* __restrict__ mask,
                                                       const int* __restrict__ normp) {
    __shared__ float row[Nn];
    __shared__ float red[256];
    const int n = blockIdx.x, tid = threadIdx.x;

    float En[16];
#pragma unroll
    for (int d = 0; d < 16; d++) En[d] = E[n * 16 + d];

    for (int m = tid; m < Nn; m += 256) {
        const float4* e4 = reinterpret_cast<const float4*>(E + m * 16);
        float v = 0.f;
#pragma unroll
        for (int q = 0; q < 4; q++) {
            float4 w = e4[q];
            v += En[4 * q + 0] * w.x + En[4 * q + 1] * w.y + En[4 * q + 2] * w.z + En[4 * q + 3] * w.w;
        }
        row[m] = fmaxf(v, 0.f);
    }
    __syncthreads();

    float lm = -1e30f;
    for (int m = tid; m < Nn; m += 256) lm = fmaxf(lm, row[m]);
    float mx = block_reduce(lm, red, tid, true);
    float ls = 0.f;
    for (int m = tid; m < Nn; m += 256) { float e = expf(row[m] - mx); row[m] = e; ls += e; }
    float sum = block_reduce(ls, red, tid, false);
    float inv = 1.f / sum;
    for (int m = tid; m < Nn; m += 256) row[m] = row[m] * inv * mask[(size_t)n * Nn + m];
    __syncthreads();

    if (*normp != 0) {
        lm = -1e30f;
        for (int m = tid; m < Nn; m += 256) lm = fmaxf(lm, row[m]);
        mx = block_reduce(lm, red, tid, true);
        ls = 0.f;
        for (int m = tid; m < Nn; m += 256) { float e = expf(row[m] - mx); row[m] = e; ls += e; }
        sum = block_reduce(ls, red, tid, false);
        inv = 1.f / sum;
        for (int m = tid; m < Nn; m += 256) row[m] *= inv;
        __syncthreads();
    }

    for (int m = tid; m < Nn; m += 256) {
        float v = row[m];
        __nv_bfloat16 h = __float2bfloat16(v);
        g_Shi[(size_t)n * Nn + m] = h;
        g_Slo[(size_t)n * Nn + m] = __float2bfloat16(v - __bfloat162float(h));
    }
}

// ---------------------------------------------------------------------------
// K2: pack. Emits node-major fp32 X0 AND transposed bf16 hi/lo planes.
// grid (Nn/32, Bb), block 256.  CAND: concat(x, z*state), z = ZR[b][n][0:H]
// ---------------------------------------------------------------------------
template <bool CAND>
__global__ void __launch_bounds__(256) pack_kernel(const float* __restrict__ x,
                                                   const float* __restrict__ st) {
    __shared__ float s[32 * 65];
    __shared__ float z[32 * 65];
    __shared__ float xt[64];
    const int n0 = blockIdx.x * 32, b = blockIdx.y, tid = threadIdx.x;

    const float* sp = st + ((size_t)b * Nn + n0) * Hh;
#pragma unroll
    for (int j = 0; j < 8; j++) {
        int e = tid + 256 * j;
        s[(e >> 6) * 65 + (e & 63)] = sp[e];
    }
    if (tid < 64) xt[tid] = x[((size_t)b * Nn + n0 + (tid >> 1)) * 2 + (tid & 1)];
    if (CAND) {
        const float* zp = g_ZR + ((size_t)b * Nn + n0) * OG;
#pragma unroll
        for (int j = 0; j < 8; j++) {
            int e = tid + 256 * j;
            z[(e >> 6) * 65 + (e & 63)] = zp[(e >> 6) * OG + (e & 63)];
        }
    }
    __syncthreads();

    for (int e = tid; e < 32 * Cc; e += 256) {
        int i = e / Cc, c = e - i * Cc;
        float v = (c < 2) ? xt[i * 2 + c]
                          : (CAND ? z[i * 65 + (c - 2)] * s[i * 65 + (c - 2)]
                                  : s[i * 65 + (c - 2)]);
        g_X0[(size_t)(n0 + i) * BC + b * Cc + c] = v;
    }
    for (int e = tid; e < Cc * 32; e += 256) {
        int c = e >> 5, i = e & 31;
        float v = (c < 2) ? xt[i * 2 + c]
                          : (CAND ? z[i * 65 + (c - 2)] * s[i * 65 + (c - 2)]
                                  : s[i * 65 + (c - 2)]);
        __nv_bfloat16 h = __float2bfloat16(v);
        size_t o = (size_t)(b * Cc + c) * Nn + n0 + i;
        g_Xth[o] = h;
        g_Xtl[o] = __float2bfloat16(v - __bfloat162float(h));
    }
}

// ---------------------------------------------------------------------------
// K3: warp-mma GEMM (unchanged from R7)
// ---------------------------------------------------------------------------
template <int EPI>
__device__ __forceinline__ void gemm_issue(unsigned smb, int tid, int row0, int col0,
                                           const __nv_bfloat16* __restrict__ Bhi,
                                           const __nv_bfloat16* __restrict__ Blo, int ch) {
    const unsigned base = smb + (unsigned)(ch & 1) * STG;
    const size_t kb = (size_t)ch * KT;
#pragma unroll
    for (int j = 0; j < 8; j++) {
        const int e = tid + (j & 1) * 256;
        const int r = e >> 2, c = e & 3;
        const unsigned d = base + (j >> 1) * PL + (unsigned)(r * 80 + c * 16);
        const __nv_bfloat16* g;
        switch (j >> 1) {
            case 0:  g = g_Shi + (size_t)(row0 + r) * Nn + kb + c * 8; break;
            case 1:  g = g_Slo + (size_t)(row0 + r) * Nn + kb + c * 8; break;
            case 2:  g = Bhi   + (size_t)(col0 + r) * Nn + kb + c * 8; break;
            default: g = Blo   + (size_t)(col0 + r) * Nn + kb + c * 8; break;
        }
        cpa16(d, g);
    }
    asm volatile("cp.async.commit_group;");
}

template <int EPI>
__global__ void __launch_bounds__(256, 2) mma_gemm(const __nv_bfloat16* __restrict__ Bhi,
                                                   const __nv_bfloat16* __restrict__ Blo,
                                                   const float* __restrict__ Cin,
                                                   float* __restrict__ Yout) {
    extern __shared__ char smem[];
    const unsigned smb = smem_u32(smem);
    const int tid = threadIdx.x, wid = tid >> 5, lane = tid & 31;
    const int col0 = blockIdx.x * NT;
    const int row0 = blockIdx.y * MT;
    const int wm = (wid >> 1) * 32;
    const int wn = (wid & 1) * 64;

    float acc[2][8][4];
#pragma unroll
    for (int f = 0; f < 2; f++)
#pragma unroll
        for (int g = 0; g < 8; g++)
#pragma unroll
            for (int q = 0; q < 4; q++) acc[f][g][q] = 0.f;

    gemm_issue<EPI>(smb, tid, row0, col0, Bhi, Blo, 0);

    const int am = wm + (lane & 15);
    const int akb = ((lane >> 4) * 8) * 2;
    const int bn = wn + ((lane >> 4) << 3) + (lane & 7);
    const int bkb = (((lane >> 3) & 1) * 8) * 2;

    for (int i = 0; i < NKC; i++) {
        if (i + 1 < NKC) {
            gemm_issue<EPI>(smb, tid, row0, col0, Bhi, Blo, i + 1);
            asm volatile("cp.async.wait_group 1;");
        } else {
            asm volatile("cp.async.wait_group 0;");
        }
        __syncthreads();

        const unsigned base = smb + (unsigned)(i & 1) * STG;
#pragma unroll
        for (int ks = 0; ks < 2; ks++) {
            unsigned Ah[2][4], Al[2][4];
#pragma unroll
            for (int f = 0; f < 2; f++) {
                const unsigned ad = base + (unsigned)((am + f * 16) * 80 + akb + ks * 32);
                ldsm4(Ah[f], ad);
                ldsm4(Al[f], ad + PL);
            }
#pragma unroll
            for (int g4 = 0; g4 < 4; g4++) {
                unsigned Bh[4], Bl[4];
                const unsigned bd = base + 2 * PL +
                                    (unsigned)((bn + g4 * 16) * 80 + bkb + ks * 32);
                ldsm4(Bh, bd);
                ldsm4(Bl, bd + PL);
#pragma unroll
                for (int f = 0; f < 2; f++) {
#pragma unroll
                    for (int h = 0; h < 2; h++) {
                        float* c = acc[f][g4 * 2 + h];
                        mma_bf16(c, Ah[f], Bh + h * 2);
                        mma_bf16(c, Ah[f], Bl + h * 2);
                        mma_bf16(c, Al[f], Bh + h * 2);
                    }
                }
            }
        }
        __syncthreads();
    }

#pragma unroll
    for (int f = 0; f < 2; f++) {
#pragma unroll
        for (int g = 0; g < 8; g++) {
            const int m = row0 + wm + f * 16 + (lane >> 2);
            const int n = col0 + wn + g * 8 + (lane & 3) * 2;
            const float* c = acc[f][g];
            const size_t o0 = (size_t)m * BC + n;
            const size_t o1 = (size_t)(m + 8) * BC + n;
            if (EPI == 0) {
                *reinterpret_cast<float2*>(&Yout[o0]) = make_float2(c[0], c[1]);
                *reinterpret_cast<float2*>(&Yout[o1]) = make_float2(c[2], c[3]);
            } else {
                float2 x0 = *reinterpret_cast<const float2*>(&Cin[o0]);
                float2 x1 = *reinterpret_cast<const float2*>(&Cin[o1]);
                *reinterpret_cast<float2*>(&Yout[o0]) =
                    make_float2(2.f * c[0] - x0.x, 2.f * c[1] - x0.y);
                *reinterpret_cast<float2*>(&Yout[o1]) =
                    make_float2(2.f * c[2] - x1.x, 2.f * c[3] - x1.y);
            }
        }
    }
}

// ---------------------------------------------------------------------------
// K4: transpose-split Y1 -> Y1^T hi/lo bf16 planes
// ---------------------------------------------------------------------------
__global__ void __launch_bounds__(256) tsplit_kernel() {
    __shared__ float t[32][33];
    const int c0 = blockIdx.x * 32, n0 = blockIdx.y * 32;
    const int tx = threadIdx.x, ty = threadIdx.y;
#pragma unroll
    for (int j = 0; j < 32; j += 8)
        t[ty + j][tx] = g_Y1[(size_t)(n0 + ty + j) * BC + c0 + tx];
    __syncthreads();
#pragma unroll
    for (int j = 0; j < 32; j += 8) {
        float v = t[tx][ty + j];
        __nv_bfloat16 h = __float2bfloat16(v);
        size_t o = (size_t)(c0 + ty + j) * Nn + n0 + tx;
        g_Yth[o] = h;
        g_Ytl[o] = __float2bfloat16(v - __bfloat162float(h));
    }
}

// ---------------------------------------------------------------------------
// K5 (R8): projection, NPB=4 nodes per block, 512 threads.
//   Per k-tile: stage xg[4][64][33] (stride 34) + build ws[4][33][O] from W
//   (each W element read ONCE per block, used for 4 nodes). FFMA2 micro-GEMM.
// GATE: ZR = sigmoid(acc + bias);  else: out = r*st + (1-r)*tanh(acc + bias)
// ---------------------------------------------------------------------------
template <int O, bool GATE>
__global__ void __launch_bounds__(512, 1) proj_kernel(const float* __restrict__ E,
                                                      const float* __restrict__ W,
                                                      const float* __restrict__ bp,
                                                      const float* __restrict__ st,
                                                      float* __restrict__ outp) {
    constexpr int OV = O / 4;            // o4 groups: gate 32, upd 16
    constexpr int NTB = 512 / OV;        // b groups:  gate 16, upd 32
    constexpr int BPT = Bb / NTB;        // b/thread:  gate 4,  upd 2
    constexpr int XST = 34;              // xg k-stride (pad for float2 align)

    extern __shared__ float sm[];
    float* xgs = sm;                     // [NPB][64][XST]
    float* wss = sm + NPB * Bb * XST;    // [NPB][TKI][O]
    __shared__ float Esh[NPB * 16];

    const int n0 = blockIdx.x * NPB, tid = threadIdx.x;
    const int to = tid % OV, tb = tid / OV;

    if (tid < NPB * 16) Esh[tid] = E[(n0 + (tid >> 4)) * 16 + (tid & 15)];

    unsigned long long acc[NPB][BPT][2];
#pragma unroll
    for (int p = 0; p < NPB; p++)
#pragma unroll
        for (int j = 0; j < BPT; j++) { acc[p][j][0] = 0ull; acc[p][j][1] = 0ull; }

    const float* bufs[3] = {g_X0, g_Y1, g_Y2};

    for (int t = 0; t < NTL; t++) {
        __syncthreads();   // previous micro done (and Esh ready on t=0)

        // stage xg tiles (coalesced 33-float runs)
        const float* src = bufs[t >> 1];
        const int coff = (t & 1) * TKI;
        for (int e = tid; e < NPB * Bb * TKI; e += 512) {
            int p = e / (Bb * TKI), r = e - p * (Bb * TKI);
            int b = r / TKI, kk = r - b * TKI;
            xgs[(p * Bb + b) * XST + kk] =
                src[(size_t)(n0 + p) * BC + b * Cc + coff + kk];
        }

        // build ws tiles: one W read -> 4 nodes
        for (int e = tid; e < TKI * OV; e += 512) {
            int kk = e / OV, o4 = e - kk * OV;
            const float* wp = W + (size_t)((t * TKI + kk) * O + o4 * 4);
            unsigned long long s0[NPB], s1[NPB];
#pragma unroll
            for (int p = 0; p < NPB; p++) { s0[p] = 0ull; s1[p] = 0ull; }
#pragma unroll
            for (int d = 0; d < 16; d++) {
                float4 w = *reinterpret_cast<const float4*>(wp + (size_t)d * KC * O);
                unsigned long long w0 = packf2(w.x, w.y), w1 = packf2(w.z, w.w);
#pragma unroll
                for (int p = 0; p < NPB; p++) {
                    unsigned long long e2 = dup2(Esh[p * 16 + d]);
                    ffma2(s0[p], e2, w0);
                    ffma2(s1[p], e2, w1);
                }
            }
#pragma unroll
            for (int p = 0; p < NPB; p++) {
                ulonglong2 ov;
                ov.x = s0[p]; ov.y = s1[p];
                *reinterpret_cast<ulonglong2*>(&wss[(p * TKI + kk) * O + o4 * 4]) = ov;
            }
        }
        __syncthreads();

        // micro-GEMM: acc[p][b][o4] += xg[p][b][kk] * ws[p][kk][o4]
        int kk = 0;
#pragma unroll 4
        for (; kk + 1 < TKI; kk += 2) {
#pragma unroll
            for (int p = 0; p < NPB; p++) {
                const float* wrow0 = &wss[(p * TKI + kk) * O + to * 4];
                const float* wrow1 = wrow0 + O;
                ulonglong2 wq0 = *reinterpret_cast<const ulonglong2*>(wrow0);
                ulonglong2 wq1 = *reinterpret_cast<const ulonglong2*>(wrow1);
#pragma unroll
                for (int j = 0; j < BPT; j++) {
                    float2 xv = *reinterpret_cast<const float2*>(
                        &xgs[(p * Bb + tb * BPT + j) * XST + kk]);
                    unsigned long long x0 = dup2(xv.x), x1 = dup2(xv.y);
                    ffma2(acc[p][j][0], x0, wq0.x);
                    ffma2(acc[p][j][1], x0, wq0.y);
                    ffma2(acc[p][j][0], x1, wq1.x);
                    ffma2(acc[p][j][1], x1, wq1.y);
                }
            }
        }
        // tail kk = 32
        {
#pragma unroll
            for (int p = 0; p < NPB; p++) {
                ulonglong2 wq = *reinterpret_cast<const ulonglong2*>(
                    &wss[(p * TKI + kk) * O + to * 4]);
#pragma unroll
                for (int j = 0; j < BPT; j++) {
                    unsigned long long xv =
                        dup2(xgs[(p * Bb + tb * BPT + j) * XST + kk]);
                    ffma2(acc[p][j][0], xv, wq.x);
                    ffma2(acc[p][j][1], xv, wq.y);
                }
            }
        }
    }

    // bias + activation + store
#pragma unroll
    for (int p = 0; p < NPB; p++) {
        float bias[4];
#pragma unroll
        for (int jo = 0; jo < 4; jo++) {
            float s = 0.f;
#pragma unroll
            for (int d = 0; d < 16; d++) s += Esh[p * 16 + d] * bp[d * O + to * 4 + jo];
            bias[jo] = s;
        }
        const int n = n0 + p;
#pragma unroll
        for (int j = 0; j < BPT; j++) {
            const int b = tb * BPT + j;
            F2u u0, u1;
            u0.u = acc[p][j][0];
            u1.u = acc[p][j][1];
            float a0 = u0.f.x + bias[0], a1 = u0.f.y + bias[1];
            float a2 = u1.f.x + bias[2], a3 = u1.f.y + bias[3];
            if (GATE) {
                float4 o;
                o.x = 1.f / (1.f + expf(-a0));
                o.y = 1.f / (1.f + expf(-a1));
                o.z = 1.f / (1.f + expf(-a2));
                o.w = 1.f / (1.f + expf(-a3));
                *reinterpret_cast<float4*>(&g_ZR[((size_t)b * Nn + n) * OG + to * 4]) = o;
            } else {
                float av[4] = {a0, a1, a2, a3};
                float vals[4];
#pragma unroll
                for (int jo = 0; jo < 4; jo++) {
                    int oo = to * 4 + jo;
                    float hc = tanhf(av[jo]);
                    float r = g_ZR[((size_t)b * Nn + n) * OG + Hh + oo];
                    float sv = st[((size_t)b * Nn + n) * Hh + oo];
                    vals[jo] = r * sv + (1.f - r) * hc;
                }
                float4 o = make_float4(vals[0], vals[1], vals[2], vals[3]);
                *reinterpret_cast<float4*>(&outp[((size_t)b * Nn + n) * Hh + to * 4]) = o;
            }
        }
    }
}

// ---------------------------------------------------------------------------
extern "C" void kernel_launch(void* const* d_in, const int* in_sizes, int n_in,
                              void* d_out, int out_size) {
    const float* x    = (const float*)d_in[0];
    const float* st   = (const float*)d_in[1];
    const float* E    = (const float*)d_in[2];
    const float* mask = (const float*)d_in[3];
    const float* gW   = (const float*)d_in[4];
    const float* gb   = (const float*)d_in[5];
    const float* uW   = (const float*)d_in[6];
    const float* ub   = (const float*)d_in[7];
    const int*   normp = (const int*)d_in[8];
    float* outp = (float*)d_out;

    void *pX0, *pY1, *pY2, *pXth, *pXtl, *pYth, *pYtl;
    cudaGetSymbolAddress(&pX0, g_X0);
    cudaGetSymbolAddress(&pY1, g_Y1);
    cudaGetSymbolAddress(&pY2, g_Y2);
    cudaGetSymbolAddress(&pXth, g_Xth);
    cudaGetSymbolAddress(&pXtl, g_Xtl);
    cudaGetSymbolAddress(&pYth, g_Yth);
    cudaGetSymbolAddress(&pYtl, g_Ytl);

    const int smem_mma = 2 * STG;                                 // 81920
    cudaFuncSetAttribute(mma_gemm<0>, cudaFuncAttributeMaxDynamicSharedMemorySize, smem_mma);
    cudaFuncSetAttribute(mma_gemm<1>, cudaFuncAttributeMaxDynamicSharedMemorySize, smem_mma);

    const int smem_g = (NPB * Bb * 34 + NPB * TKI * OG) * 4;      // 102400
    const int smem_u = (NPB * Bb * 34 + NPB * TKI * OU) * 4;      // 68608
    cudaFuncSetAttribute(proj_kernel<OG, true>, cudaFuncAttributeMaxDynamicSharedMemorySize, smem_g);
    cudaFuncSetAttribute(proj_kernel<OU, false>, cudaFuncAttributeMaxDynamicSharedMemorySize, smem_u);

    dim3 gg(BC / NT, Nn / MT);                   // (33, 16)
    dim3 pg(Nn / 32, Bb);                        // (64, 64)
    dim3 tg(BC / 32, Nn / 32);                   // (132, 64)

    supports_kernel<<<Nn, 256>>>(E, mask, normp);

    // gate GCN
    pack_kernel<false><<<pg, 256>>>(x, st);
    mma_gemm<0><<<gg, 256, smem_mma>>>((const __nv_bfloat16*)pXth, (const __nv_bfloat16*)pXtl,
                                       nullptr, (float*)pY1);
    tsplit_kernel<<<tg, dim3(32, 8)>>>();
    mma_gemm<1><<<gg, 256, smem_mma>>>((const __nv_bfloat16*)pYth, (const __nv_bfloat16*)pYtl,
                                       (const float*)pX0, (float*)pY2);
    proj_kernel<OG, true><<<Nn / NPB, 512, smem_g>>>(E, gW, gb, nullptr, nullptr);

    // candidate GCN + GRU combine
    pack_kernel<true><<<pg, 256>>>(x, st);
    mma_gemm<0><<<gg, 256, smem_mma>>>((const __nv_bfloat16*)pXth, (const __nv_bfloat16*)pXtl,
                                       nullptr, (float*)pY1);
    tsplit_kernel<<<tg, dim3(32, 8)>>>();
    mma_gemm<1><<<gg, 256, smem_mma>>>((const __nv_bfloat16*)pYth, (const __nv_bfloat16*)pYtl,
                                       (const float*)pX0, (float*)pY2);
    proj_kernel<OU, false><<<Nn / NPB, 512, smem_u>>>(E, uW, ub, st, outp);
}

// round 13
// speedup vs baseline: 1.1197x; 1.1197x over previous
#include <cuda_runtime.h>
#include <cuda_bf16.h>
#include <math.h>

// ---------------------------------------------------------------------------
// AGCRN cell, B=64, N=2048, Din=2, H=64, K=3, D=16.
// R12: GEMMs on mma.sync bf16x3 (unchanged, proven 1981us config).
// Projection: R7 structure + NPB=2 nodes/block (W L2 traffic /2) + FFMA2.
// ---------------------------------------------------------------------------

#define Nn 2048
#define Bb 64
#define Cc 66
#define BC 4224             // Bb * Cc = 33 * 128
#define KC 198              // 3 * Cc
#define OG 128
#define OU 64
#define Hh 64

#define MT 128              // GEMM m-tile (nodes)
#define NT 128              // GEMM n-tile (bc columns)
#define KT 32               // k per stage
#define NKC (Nn / KT)       // 64 stages
#define PL 10240            // bytes per smem plane: 128 rows * 80B
#define STG (4 * PL)        // 40960 bytes per pipeline stage

#define TKI 33              // proj k-tile

// scratch (__device__ globals)
__device__ __nv_bfloat16 g_Shi[(size_t)Nn * Nn];   // S hi plane (k-major rows)
__device__ __nv_bfloat16 g_Slo[(size_t)Nn * Nn];
__device__ __nv_bfloat16 g_Xth[(size_t)BC * Nn];   // X^T hi (bc-major rows)
__device__ __nv_bfloat16 g_Xtl[(size_t)BC * Nn];
__device__ __nv_bfloat16 g_Yth[(size_t)BC * Nn];   // Y1^T hi
__device__ __nv_bfloat16 g_Ytl[(size_t)BC * Nn];
__device__ float g_X0[(size_t)Nn * BC];            // node-major fp32
__device__ float g_Y1[(size_t)Nn * BC];
__device__ float g_Y2[(size_t)Nn * BC];
__device__ float g_ZR[(size_t)Bb * Nn * OG];       // gate out, [b][n][2H]

// ---------------------------------------------------------------------------
// PTX helpers (plain-sm_103-legal)
// ---------------------------------------------------------------------------
__device__ __forceinline__ unsigned smem_u32(const void* p) {
    unsigned a;
    asm("{ .reg .u64 t; cvta.to.shared.u64 t, %1; cvt.u32.u64 %0, t; }" : "=r"(a) : "l"(p));
    return a;
}
__device__ __forceinline__ void cpa16(unsigned dst, const void* src) {
    asm volatile("cp.async.cg.shared.global [%0], [%1], 16;" :: "r"(dst), "l"(src));
}
__device__ __forceinline__ void ldsm4(unsigned* r, unsigned a) {
    asm volatile("ldmatrix.sync.aligned.m8n8.x4.shared.b16 {%0,%1,%2,%3}, [%4];"
                 : "=r"(r[0]), "=r"(r[1]), "=r"(r[2]), "=r"(r[3]) : "r"(a));
}
__device__ __forceinline__ void mma_bf16(float* c, const unsigned* a, const unsigned* b) {
    asm volatile(
        "mma.sync.aligned.m16n8k16.row.col.f32.bf16.bf16.f32 "
        "{%0,%1,%2,%3}, {%4,%5,%6,%7}, {%8,%9}, {%0,%1,%2,%3};"
        : "+f"(c[0]), "+f"(c[1]), "+f"(c[2]), "+f"(c[3])
        : "r"(a[0]), "r"(a[1]), "r"(a[2]), "r"(a[3]), "r"(b[0]), "r"(b[1]));
}
__device__ __forceinline__ void ffma2(unsigned long long& d, unsigned long long a,
                                      unsigned long long b) {
    asm("fma.rn.f32x2 %0, %1, %2, %0;" : "+l"(d) : "l"(a), "l"(b));
}
__device__ __forceinline__ unsigned long long dup2(float v) {
    unsigned long long r;
    unsigned u = __float_as_uint(v);
    asm("mov.b64 %0, {%1, %1};" : "=l"(r) : "r"(u));
    return r;
}
__device__ __forceinline__ unsigned long long packf2(float x, float y) {
    unsigned long long r;
    asm("mov.b64 %0, {%1, %2};" : "=l"(r) : "r"(__float_as_uint(x)), "r"(__float_as_uint(y)));
    return r;
}
union F2u { unsigned long long u; float2 f; };

// ---------------------------------------------------------------------------
// K1: supports (one block per row n)  -> bf16 hi/lo planes of S
// ---------------------------------------------------------------------------
__device__ __forceinline__ float block_reduce(float v, float* red, int tid, bool ismax) {
    red[tid] = v;
    __syncthreads();
    for (int s = 128; s > 0; s >>= 1) {
        if (tid < s) red[tid] = ismax ? fmaxf(red[tid], red[tid + s]) : (red[tid] + red[tid + s]);
        __syncthreads();
    }
    float r = red[0];
    __syncthreads();
    return r;
}

__global__ void __launch_bounds__(256) supports_kernel(const float* __restrict__ E,
                                                       const float* __restrict__ mask,
                                                       const int* __restrict__ normp) {
    __shared__ float row[Nn];
    __shared__ float red[256];
    const int n = blockIdx.x, tid = threadIdx.x;

    float En[16];
#pragma unroll
    for (int d = 0; d < 16; d++) En[d] = E[n * 16 + d];

    for (int m = tid; m < Nn; m += 256) {
        const float4* e4 = reinterpret_cast<const float4*>(E + m * 16);
        float v = 0.f;
#pragma unroll
        for (int q = 0; q < 4; q++) {
            float4 w = e4[q];
            v += En[4 * q + 0] * w.x + En[4 * q + 1] * w.y + En[4 * q + 2] * w.z + En[4 * q + 3] * w.w;
        }
        row[m] = fmaxf(v, 0.f);
    }
    __syncthreads();

    float lm = -1e30f;
    for (int m = tid; m < Nn; m += 256) lm = fmaxf(lm, row[m]);
    float mx = block_reduce(lm, red, tid, true);
    float ls = 0.f;
    for (int m = tid; m < Nn; m += 256) { float e = expf(row[m] - mx); row[m] = e; ls += e; }
    float sum = block_reduce(ls, red, tid, false);
    float inv = 1.f / sum;
    for (int m = tid; m < Nn; m += 256) row[m] = row[m] * inv * mask[(size_t)n * Nn + m];
    __syncthreads();

    if (*normp != 0) {
        lm = -1e30f;
        for (int m = tid; m < Nn; m += 256) lm = fmaxf(lm, row[m]);
        mx = block_reduce(lm, red, tid, true);
        ls = 0.f;
        for (int m = tid; m < Nn; m += 256) { float e = expf(row[m] - mx); row[m] = e; ls += e; }
        sum = block_reduce(ls, red, tid, false);
        inv = 1.f / sum;
        for (int m = tid; m < Nn; m += 256) row[m] *= inv;
        __syncthreads();
    }

    for (int m = tid; m < Nn; m += 256) {
        float v = row[m];
        __nv_bfloat16 h = __float2bfloat16(v);
        g_Shi[(size_t)n * Nn + m] = h;
        g_Slo[(size_t)n * Nn + m] = __float2bfloat16(v - __bfloat162float(h));
    }
}

// ---------------------------------------------------------------------------
// K2: pack. Emits node-major fp32 X0 AND transposed bf16 hi/lo planes.
// grid (Nn/32, Bb), block 256.  CAND: concat(x, z*state), z = ZR[b][n][0:H]
// ---------------------------------------------------------------------------
template <bool CAND>
__global__ void __launch_bounds__(256) pack_kernel(const float* __restrict__ x,
                                                   const float* __restrict__ st) {
    __shared__ float s[32 * 65];
    __shared__ float z[32 * 65];
    __shared__ float xt[64];
    const int n0 = blockIdx.x * 32, b = blockIdx.y, tid = threadIdx.x;

    const float* sp = st + ((size_t)b * Nn + n0) * Hh;
#pragma unroll
    for (int j = 0; j < 8; j++) {
        int e = tid + 256 * j;
        s[(e >> 6) * 65 + (e & 63)] = sp[e];
    }
    if (tid < 64) xt[tid] = x[((size_t)b * Nn + n0 + (tid >> 1)) * 2 + (tid & 1)];
    if (CAND) {
        const float* zp = g_ZR + ((size_t)b * Nn + n0) * OG;
#pragma unroll
        for (int j = 0; j < 8; j++) {
            int e = tid + 256 * j;
            z[(e >> 6) * 65 + (e & 63)] = zp[(e >> 6) * OG + (e & 63)];
        }
    }
    __syncthreads();

    for (int e = tid; e < 32 * Cc; e += 256) {
        int i = e / Cc, c = e - i * Cc;
        float v = (c < 2) ? xt[i * 2 + c]
                          : (CAND ? z[i * 65 + (c - 2)] * s[i * 65 + (c - 2)]
                                  : s[i * 65 + (c - 2)]);
        g_X0[(size_t)(n0 + i) * BC + b * Cc + c] = v;
    }
    for (int e = tid; e < Cc * 32; e += 256) {
        int c = e >> 5, i = e & 31;
        float v = (c < 2) ? xt[i * 2 + c]
                          : (CAND ? z[i * 65 + (c - 2)] * s[i * 65 + (c - 2)]
                                  : s[i * 65 + (c - 2)]);
        __nv_bfloat16 h = __float2bfloat16(v);
        size_t o = (size_t)(b * Cc + c) * Nn + n0 + i;
        g_Xth[o] = h;
        g_Xtl[o] = __float2bfloat16(v - __bfloat162float(h));
    }
}

// ---------------------------------------------------------------------------
// K3: warp-mma GEMM (unchanged, proven)
// ---------------------------------------------------------------------------
template <int EPI>
__device__ __forceinline__ void gemm_issue(unsigned smb, int tid, int row0, int col0,
                                           const __nv_bfloat16* __restrict__ Bhi,
                                           const __nv_bfloat16* __restrict__ Blo, int ch) {
    const unsigned base = smb + (unsigned)(ch & 1) * STG;
    const size_t kb = (size_t)ch * KT;
#pragma unroll
    for (int j = 0; j < 8; j++) {
        const int e = tid + (j & 1) * 256;
        const int r = e >> 2, c = e & 3;
        const unsigned d = base + (j >> 1) * PL + (unsigned)(r * 80 + c * 16);
        const __nv_bfloat16* g;
        switch (j >> 1) {
            case 0:  g = g_Shi + (size_t)(row0 + r) * Nn + kb + c * 8; break;
            case 1:  g = g_Slo + (size_t)(row0 + r) * Nn + kb + c * 8; break;
            case 2:  g = Bhi   + (size_t)(col0 + r) * Nn + kb + c * 8; break;
            default: g = Blo   + (size_t)(col0 + r) * Nn + kb + c * 8; break;
        }
        cpa16(d, g);
    }
    asm volatile("cp.async.commit_group;");
}

template <int EPI>
__global__ void __launch_bounds__(256, 2) mma_gemm(const __nv_bfloat16* __restrict__ Bhi,
                                                   const __nv_bfloat16* __restrict__ Blo,
                                                   const float* __restrict__ Cin,
                                                   float* __restrict__ Yout) {
    extern __shared__ char smem[];
    const unsigned smb = smem_u32(smem);
    const int tid = threadIdx.x, wid = tid >> 5, lane = tid & 31;
    const int col0 = blockIdx.x * NT;
    const int row0 = blockIdx.y * MT;
    const int wm = (wid >> 1) * 32;
    const int wn = (wid & 1) * 64;

    float acc[2][8][4];
#pragma unroll
    for (int f = 0; f < 2; f++)
#pragma unroll
        for (int g = 0; g < 8; g++)
#pragma unroll
            for (int q = 0; q < 4; q++) acc[f][g][q] = 0.f;

    gemm_issue<EPI>(smb, tid, row0, col0, Bhi, Blo, 0);

    const int am = wm + (lane & 15);
    const int akb = ((lane >> 4) * 8) * 2;
    const int bn = wn + ((lane >> 4) << 3) + (lane & 7);
    const int bkb = (((lane >> 3) & 1) * 8) * 2;

    for (int i = 0; i < NKC; i++) {
        if (i + 1 < NKC) {
            gemm_issue<EPI>(smb, tid, row0, col0, Bhi, Blo, i + 1);
            asm volatile("cp.async.wait_group 1;");
        } else {
            asm volatile("cp.async.wait_group 0;");
        }
        __syncthreads();

        const unsigned base = smb + (unsigned)(i & 1) * STG;
#pragma unroll
        for (int ks = 0; ks < 2; ks++) {
            unsigned Ah[2][4], Al[2][4];
#pragma unroll
            for (int f = 0; f < 2; f++) {
                const unsigned ad = base + (unsigned)((am + f * 16) * 80 + akb + ks * 32);
                ldsm4(Ah[f], ad);
                ldsm4(Al[f], ad + PL);
            }
#pragma unroll
            for (int g4 = 0; g4 < 4; g4++) {
                unsigned Bh[4], Bl[4];
                const unsigned bd = base + 2 * PL +
                                    (unsigned)((bn + g4 * 16) * 80 + bkb + ks * 32);
                ldsm4(Bh, bd);
                ldsm4(Bl, bd + PL);
#pragma unroll
                for (int f = 0; f < 2; f++) {
#pragma unroll
                    for (int h = 0; h < 2; h++) {
                        float* c = acc[f][g4 * 2 + h];
                        mma_bf16(c, Ah[f], Bh + h * 2);
                        mma_bf16(c, Ah[f], Bl + h * 2);
                        mma_bf16(c, Al[f], Bh + h * 2);
                    }
                }
            }
        }
        __syncthreads();
    }

#pragma unroll
    for (int f = 0; f < 2; f++) {
#pragma unroll
        for (int g = 0; g < 8; g++) {
            const int m = row0 + wm + f * 16 + (lane >> 2);
            const int n = col0 + wn + g * 8 + (lane & 3) * 2;
            const float* c = acc[f][g];
            const size_t o0 = (size_t)m * BC + n;
            const size_t o1 = (size_t)(m + 8) * BC + n;
            if (EPI == 0) {
                *reinterpret_cast<float2*>(&Yout[o0]) = make_float2(c[0], c[1]);
                *reinterpret_cast<float2*>(&Yout[o1]) = make_float2(c[2], c[3]);
            } else {
                float2 x0 = *reinterpret_cast<const float2*>(&Cin[o0]);
                float2 x1 = *reinterpret_cast<const float2*>(&Cin[o1]);
                *reinterpret_cast<float2*>(&Yout[o0]) =
                    make_float2(2.f * c[0] - x0.x, 2.f * c[1] - x0.y);
                *reinterpret_cast<float2*>(&Yout[o1]) =
                    make_float2(2.f * c[2] - x1.x, 2.f * c[3] - x1.y);
            }
        }
    }
}

// ---------------------------------------------------------------------------
// K4: transpose-split Y1 -> Y1^T hi/lo bf16 planes (unchanged)
// ---------------------------------------------------------------------------
__global__ void __launch_bounds__(256) tsplit_kernel() {
    __shared__ float t[32][33];
    const int c0 = blockIdx.x * 32, n0 = blockIdx.y * 32;
    const int tx = threadIdx.x, ty = threadIdx.y;
#pragma unroll
    for (int j = 0; j < 32; j += 8)
        t[ty + j][tx] = g_Y1[(size_t)(n0 + ty + j) * BC + c0 + tx];
    __syncthreads();
#pragma unroll
    for (int j = 0; j < 32; j += 8) {
        float v = t[tx][ty + j];
        __nv_bfloat16 h = __float2bfloat16(v);
        size_t o = (size_t)(c0 + ty + j) * Nn + n0 + tx;
        g_Yth[o] = h;
        g_Ytl[o] = __float2bfloat16(v - __bfloat162float(h));
    }
}

// ---------------------------------------------------------------------------
// K5 (R12): projection, R7 structure, NPB=2 nodes per 256-thread block.
//   xg loaded ONCE ([2][64][198] smem). Per k-tile: ws built for both nodes
//   from a single W read (traffic /2), FFMA2 micro-GEMM.
// GATE: ZR = sigmoid(acc + bias);  else: out = r*st + (1-r)*tanh(acc + bias)
// ---------------------------------------------------------------------------
template <int O, bool GATE>
__global__ void __launch_bounds__(256, 1) proj_kernel(const float* __restrict__ E,
                                                      const float* __restrict__ W,
                                                      const float* __restrict__ bp,
                                                      const float* __restrict__ st,
                                                      float* __restrict__ outp) {
    constexpr int OV = O / 4;            // gate 32, upd 16
    constexpr int NBG = 256 / OV;        // gate 8,  upd 16
    constexpr int BPT = Bb / NBG;        // gate 8,  upd 4

    extern __shared__ float sm[];
    float* xg = sm;                      // [2][64][KC]
    float* ws = sm + 2 * Bb * KC;        // [2][TKI][O]
    __shared__ float Esh[32];

    const int n0 = blockIdx.x * 2, tid = threadIdx.x;
    const int to = tid % OV, tb = tid / OV;

    if (tid < 32) Esh[tid] = E[n0 * 16 + tid];

    const float* bufs[3] = {g_X0, g_Y1, g_Y2};
#pragma unroll
    for (int p = 0; p < 2; p++) {
#pragma unroll
        for (int k = 0; k < 3; k++) {
            const float* src = bufs[k] + (size_t)(n0 + p) * BC;
            for (int e = tid; e < Bb * Cc; e += 256) {
                int b = e / Cc, i = e - b * Cc;
                xg[(p * Bb + b) * KC + k * Cc + i] = src[e];
            }
        }
    }
    __syncthreads();

    unsigned long long acc[2][BPT][2];
#pragma unroll
    for (int p = 0; p < 2; p++)
#pragma unroll
        for (int j = 0; j < BPT; j++) { acc[p][j][0] = 0ull; acc[p][j][1] = 0ull; }

    for (int kt = 0; kt < KC; kt += TKI) {
        // build ws for both nodes; each W element read once
        for (int e = tid; e < TKI * OV; e += 256) {
            int kk = e / OV, o4 = e - kk * OV;
            const float* wp = W + (size_t)(kt + kk) * O + o4 * 4;
            unsigned long long s0[2] = {0ull, 0ull}, s1[2] = {0ull, 0ull};
#pragma unroll
            for (int d = 0; d < 16; d++) {
                float4 w = *reinterpret_cast<const float4*>(wp + (size_t)d * KC * O);
                unsigned long long w0 = packf2(w.x, w.y), w1 = packf2(w.z, w.w);
#pragma unroll
                for (int p = 0; p < 2; p++) {
                    unsigned long long e2 = dup2(Esh[p * 16 + d]);
                    ffma2(s0[p], e2, w0);
                    ffma2(s1[p], e2, w1);
                }
            }
#pragma unroll
            for (int p = 0; p < 2; p++) {
                ulonglong2 ov;
                ov.x = s0[p];
                ov.y = s1[p];
                *reinterpret_cast<ulonglong2*>(&ws[(p * TKI + kk) * O + o4 * 4]) = ov;
            }
        }
        __syncthreads();

        for (int kk = 0; kk < TKI; kk++) {
#pragma unroll
            for (int p = 0; p < 2; p++) {
                ulonglong2 wq = *reinterpret_cast<const ulonglong2*>(
                    &ws[(p * TKI + kk) * O + to * 4]);
#pragma unroll
                for (int j = 0; j < BPT; j++) {
                    unsigned long long xv =
                        dup2(xg[(p * Bb + tb * BPT + j) * KC + kt + kk]);
                    ffma2(acc[p][j][0], xv, wq.x);
                    ffma2(acc[p][j][1], xv, wq.y);
                }
            }
        }
        __syncthreads();
    }

    // bias + activation + store
#pragma unroll
    for (int p = 0; p < 2; p++) {
        float bias[4];
#pragma unroll
        for (int jo = 0; jo < 4; jo++) {
            float s = 0.f;
#pragma unroll
            for (int d = 0; d < 16; d++) s += Esh[p * 16 + d] * bp[d * O + to * 4 + jo];
            bias[jo] = s;
        }
        const int n = n0 + p;
#pragma unroll
        for (int j = 0; j < BPT; j++) {
            const int b = tb * BPT + j;
            F2u u0, u1;
            u0.u = acc[p][j][0];
            u1.u = acc[p][j][1];
            float a0 = u0.f.x + bias[0], a1 = u0.f.y + bias[1];
            float a2 = u1.f.x + bias[2], a3 = u1.f.y + bias[3];
            if (GATE) {
                float4 o;
                o.x = 1.f / (1.f + expf(-a0));
                o.y = 1.f / (1.f + expf(-a1));
                o.z = 1.f / (1.f + expf(-a2));
                o.w = 1.f / (1.f + expf(-a3));
                *reinterpret_cast<float4*>(&g_ZR[((size_t)b * Nn + n) * OG + to * 4]) = o;
            } else {
                float av[4] = {a0, a1, a2, a3};
                float vals[4];
#pragma unroll
                for (int jo = 0; jo < 4; jo++) {
                    int oo = to * 4 + jo;
                    float hc = tanhf(av[jo]);
                    float r = g_ZR[((size_t)b * Nn + n) * OG + Hh + oo];
                    float sv = st[((size_t)b * Nn + n) * Hh + oo];
                    vals[jo] = r * sv + (1.f - r) * hc;
                }
                float4 o = make_float4(vals[0], vals[1], vals[2], vals[3]);
                *reinterpret_cast<float4*>(&outp[((size_t)b * Nn + n) * Hh + to * 4]) = o;
            }
        }
    }
}

// ---------------------------------------------------------------------------
extern "C" void kernel_launch(void* const* d_in, const int* in_sizes, int n_in,
                              void* d_out, int out_size) {
    const float* x    = (const float*)d_in[0];
    const float* st   = (const float*)d_in[1];
    const float* E    = (const float*)d_in[2];
    const float* mask = (const float*)d_in[3];
    const float* gW   = (const float*)d_in[4];
    const float* gb   = (const float*)d_in[5];
    const float* uW   = (const float*)d_in[6];
    const float* ub   = (const float*)d_in[7];
    const int*   normp = (const int*)d_in[8];
    float* outp = (float*)d_out;

    void *pX0, *pY1, *pY2, *pXth, *pXtl, *pYth, *pYtl;
    cudaGetSymbolAddress(&pX0, g_X0);
    cudaGetSymbolAddress(&pY1, g_Y1);
    cudaGetSymbolAddress(&pY2, g_Y2);
    cudaGetSymbolAddress(&pXth, g_Xth);
    cudaGetSymbolAddress(&pXtl, g_Xtl);
    cudaGetSymbolAddress(&pYth, g_Yth);
    cudaGetSymbolAddress(&pYtl, g_Ytl);

    const int smem_mma = 2 * STG;                                 // 81920
    cudaFuncSetAttribute(mma_gemm<0>, cudaFuncAttributeMaxDynamicSharedMemorySize, smem_mma);
    cudaFuncSetAttribute(mma_gemm<1>, cudaFuncAttributeMaxDynamicSharedMemorySize, smem_mma);

    const int smem_g = (2 * Bb * KC + 2 * TKI * OG) * 4;          // 135168
    const int smem_u = (2 * Bb * KC + 2 * TKI * OU) * 4;          // 118272
    cudaFuncSetAttribute(proj_kernel<OG, true>, cudaFuncAttributeMaxDynamicSharedMemorySize, smem_g);
    cudaFuncSetAttribute(proj_kernel<OU, false>, cudaFuncAttributeMaxDynamicSharedMemorySize, smem_u);

    dim3 gg(BC / NT, Nn / MT);                   // (33, 16)
    dim3 pg(Nn / 32, Bb);                        // (64, 64)
    dim3 tg(BC / 32, Nn / 32);                   // (132, 64)

    supports_kernel<<<Nn, 256>>>(E, mask, normp);

    // gate GCN
    pack_kernel<false><<<pg, 256>>>(x, st);
    mma_gemm<0><<<gg, 256, smem_mma>>>((const __nv_bfloat16*)pXth, (const __nv_bfloat16*)pXtl,
                                       nullptr, (float*)pY1);
    tsplit_kernel<<<tg, dim3(32, 8)>>>();
    mma_gemm<1><<<gg, 256, smem_mma>>>((const __nv_bfloat16*)pYth, (const __nv_bfloat16*)pYtl,
                                       (const float*)pX0, (float*)pY2);
    proj_kernel<OG, true><<<Nn / 2, 256, smem_g>>>(E, gW, gb, nullptr, nullptr);

    // candidate GCN + GRU combine
    pack_kernel<true><<<pg, 256>>>(x, st);
    mma_gemm<0><<<gg, 256, smem_mma>>>((const __nv_bfloat16*)pXth, (const __nv_bfloat16*)pXtl,
                                       nullptr, (float*)pY1);
    tsplit_kernel<<<tg, dim3(32, 8)>>>();
    mma_gemm<1><<<gg, 256, smem_mma>>>((const __nv_bfloat16*)pYth, (const __nv_bfloat16*)pYtl,
                                       (const float*)pX0, (float*)pY2);
    proj_kernel<OU, false><<<Nn / 2, 256, smem_u>>>(E, uW, ub, st, outp);
}

// round 14
// speedup vs baseline: 1.1959x; 1.0681x over previous
#include <cuda_runtime.h>
#include <cuda_bf16.h>
#include <math.h>

// ---------------------------------------------------------------------------
// AGCRN cell, B=64, N=2048, Din=2, H=64, K=3, D=16.
// R13: exact R8 (1981us) configuration; proj inner loops converted to packed
// fma.rn.f32x2 with zero layout/occupancy change.
// ---------------------------------------------------------------------------

#define Nn 2048
#define Bb 64
#define Cc 66
#define BC 4224             // Bb * Cc = 33 * 128
#define KC 198              // 3 * Cc
#define OG 128
#define OU 64
#define Hh 64

#define MT 128              // GEMM m-tile (nodes)
#define NT 128              // GEMM n-tile (bc columns)
#define KT 32               // k per stage
#define NKC (Nn / KT)       // 64 stages
#define PL 10240            // bytes per smem plane: 128 rows * 80B
#define STG (4 * PL)        // 40960 bytes per pipeline stage

#define TKI 33              // proj k-tile

// scratch (__device__ globals)
__device__ __nv_bfloat16 g_Shi[(size_t)Nn * Nn];   // S hi plane (k-major rows)
__device__ __nv_bfloat16 g_Slo[(size_t)Nn * Nn];
__device__ __nv_bfloat16 g_Xth[(size_t)BC * Nn];   // X^T hi (bc-major rows)
__device__ __nv_bfloat16 g_Xtl[(size_t)BC * Nn];
__device__ __nv_bfloat16 g_Yth[(size_t)BC * Nn];   // Y1^T hi
__device__ __nv_bfloat16 g_Ytl[(size_t)BC * Nn];
__device__ float g_X0[(size_t)Nn * BC];            // node-major fp32
__device__ float g_Y1[(size_t)Nn * BC];
__device__ float g_Y2[(size_t)Nn * BC];
__device__ float g_ZR[(size_t)Bb * Nn * OG];       // gate out, [b][n][2H]

// ---------------------------------------------------------------------------
// PTX helpers (plain-sm_103-legal)
// ---------------------------------------------------------------------------
__device__ __forceinline__ unsigned smem_u32(const void* p) {
    unsigned a;
    asm("{ .reg .u64 t; cvta.to.shared.u64 t, %1; cvt.u32.u64 %0, t; }" : "=r"(a) : "l"(p));
    return a;
}
__device__ __forceinline__ void cpa16(unsigned dst, const void* src) {
    asm volatile("cp.async.cg.shared.global [%0], [%1], 16;" :: "r"(dst), "l"(src));
}
__device__ __forceinline__ void ldsm4(unsigned* r, unsigned a) {
    asm volatile("ldmatrix.sync.aligned.m8n8.x4.shared.b16 {%0,%1,%2,%3}, [%4];"
                 : "=r"(r[0]), "=r"(r[1]), "=r"(r[2]), "=r"(r[3]) : "r"(a));
}
__device__ __forceinline__ void mma_bf16(float* c, const unsigned* a, const unsigned* b) {
    asm volatile(
        "mma.sync.aligned.m16n8k16.row.col.f32.bf16.bf16.f32 "
        "{%0,%1,%2,%3}, {%4,%5,%6,%7}, {%8,%9}, {%0,%1,%2,%3};"
        : "+f"(c[0]), "+f"(c[1]), "+f"(c[2]), "+f"(c[3])
        : "r"(a[0]), "r"(a[1]), "r"(a[2]), "r"(a[3]), "r"(b[0]), "r"(b[1]));
}
__device__ __forceinline__ void ffma2(unsigned long long& d, unsigned long long a,
                                      unsigned long long b) {
    asm("fma.rn.f32x2 %0, %1, %2, %0;" : "+l"(d) : "l"(a), "l"(b));
}
__device__ __forceinline__ unsigned long long dup2(float v) {
    unsigned long long r;
    unsigned u = __float_as_uint(v);
    asm("mov.b64 %0, {%1, %1};" : "=l"(r) : "r"(u));
    return r;
}
__device__ __forceinline__ unsigned long long packf2(float x, float y) {
    unsigned long long r;
    asm("mov.b64 %0, {%1, %2};" : "=l"(r) : "r"(__float_as_uint(x)), "r"(__float_as_uint(y)));
    return r;
}
union F2u { unsigned long long u; float2 f; };

// ---------------------------------------------------------------------------
// K1: supports (one block per row n)  -> bf16 hi/lo planes of S
// ---------------------------------------------------------------------------
__device__ __forceinline__ float block_reduce(float v, float* red, int tid, bool ismax) {
    red[tid] = v;
    __syncthreads();
    for (int s = 128; s > 0; s >>= 1) {
        if (tid < s) red[tid] = ismax ? fmaxf(red[tid], red[tid + s]) : (red[tid] + red[tid + s]);
        __syncthreads();
    }
    float r = red[0];
    __syncthreads();
    return r;
}

__global__ void __launch_bounds__(256) supports_kernel(const float* __restrict__ E,
                                                       const float* __restrict__ mask,
                                                       const int* __restrict__ normp) {
    __shared__ float row[Nn];
    __shared__ float red[256];
    const int n = blockIdx.x, tid = threadIdx.x;

    float En[16];
#pragma unroll
    for (int d = 0; d < 16; d++) En[d] = E[n * 16 + d];

    for (int m = tid; m < Nn; m += 256) {
        const float4* e4 = reinterpret_cast<const float4*>(E + m * 16);
        float v = 0.f;
#pragma unroll
        for (int q = 0; q < 4; q++) {
            float4 w = e4[q];
            v += En[4 * q + 0] * w.x + En[4 * q + 1] * w.y + En[4 * q + 2] * w.z + En[4 * q + 3] * w.w;
        }
        row[m] = fmaxf(v, 0.f);
    }
    __syncthreads();

    float lm = -1e30f;
    for (int m = tid; m < Nn; m += 256) lm = fmaxf(lm, row[m]);
    float mx = block_reduce(lm, red, tid, true);
    float ls = 0.f;
    for (int m = tid; m < Nn; m += 256) { float e = expf(row[m] - mx); row[m] = e; ls += e; }
    float sum = block_reduce(ls, red, tid, false);
    float inv = 1.f / sum;
    for (int m = tid; m < Nn; m += 256) row[m] = row[m] * inv * mask[(size_t)n * Nn + m];
    __syncthreads();

    if (*normp != 0) {
        lm = -1e30f;
        for (int m = tid; m < Nn; m += 256) lm = fmaxf(lm, row[m]);
        mx = block_reduce(lm, red, tid, true);
        ls = 0.f;
        for (int m = tid; m < Nn; m += 256) { float e = expf(row[m] - mx); row[m] = e; ls += e; }
        sum = block_reduce(ls, red, tid, false);
        inv = 1.f / sum;
        for (int m = tid; m < Nn; m += 256) row[m] *= inv;
        __syncthreads();
    }

    for (int m = tid; m < Nn; m += 256) {
        float v = row[m];
        __nv_bfloat16 h = __float2bfloat16(v);
        g_Shi[(size_t)n * Nn + m] = h;
        g_Slo[(size_t)n * Nn + m] = __float2bfloat16(v - __bfloat162float(h));
    }
}

// ---------------------------------------------------------------------------
// K2: pack. Emits node-major fp32 X0 AND transposed bf16 hi/lo planes.
// grid (Nn/32, Bb), block 256.  CAND: concat(x, z*state), z = ZR[b][n][0:H]
// ---------------------------------------------------------------------------
template <bool CAND>
__global__ void __launch_bounds__(256) pack_kernel(const float* __restrict__ x,
                                                   const float* __restrict__ st) {
    __shared__ float s[32 * 65];
    __shared__ float z[32 * 65];
    __shared__ float xt[64];
    const int n0 = blockIdx.x * 32, b = blockIdx.y, tid = threadIdx.x;

    const float* sp = st + ((size_t)b * Nn + n0) * Hh;
#pragma unroll
    for (int j = 0; j < 8; j++) {
        int e = tid + 256 * j;
        s[(e >> 6) * 65 + (e & 63)] = sp[e];
    }
    if (tid < 64) xt[tid] = x[((size_t)b * Nn + n0 + (tid >> 1)) * 2 + (tid & 1)];
    if (CAND) {
        const float* zp = g_ZR + ((size_t)b * Nn + n0) * OG;
#pragma unroll
        for (int j = 0; j < 8; j++) {
            int e = tid + 256 * j;
            z[(e >> 6) * 65 + (e & 63)] = zp[(e >> 6) * OG + (e & 63)];
        }
    }
    __syncthreads();

    for (int e = tid; e < 32 * Cc; e += 256) {
        int i = e / Cc, c = e - i * Cc;
        float v = (c < 2) ? xt[i * 2 + c]
                          : (CAND ? z[i * 65 + (c - 2)] * s[i * 65 + (c - 2)]
                                  : s[i * 65 + (c - 2)]);
        g_X0[(size_t)(n0 + i) * BC + b * Cc + c] = v;
    }
    for (int e = tid; e < Cc * 32; e += 256) {
        int c = e >> 5, i = e & 31;
        float v = (c < 2) ? xt[i * 2 + c]
                          : (CAND ? z[i * 65 + (c - 2)] * s[i * 65 + (c - 2)]
                                  : s[i * 65 + (c - 2)]);
        __nv_bfloat16 h = __float2bfloat16(v);
        size_t o = (size_t)(b * Cc + c) * Nn + n0 + i;
        g_Xth[o] = h;
        g_Xtl[o] = __float2bfloat16(v - __bfloat162float(h));
    }
}

// ---------------------------------------------------------------------------
// K3: warp-mma GEMM (unchanged, proven)
// ---------------------------------------------------------------------------
template <int EPI>
__device__ __forceinline__ void gemm_issue(unsigned smb, int tid, int row0, int col0,
                                           const __nv_bfloat16* __restrict__ Bhi,
                                           const __nv_bfloat16* __restrict__ Blo, int ch) {
    const unsigned base = smb + (unsigned)(ch & 1) * STG;
    const size_t kb = (size_t)ch * KT;
#pragma unroll
    for (int j = 0; j < 8; j++) {
        const int e = tid + (j & 1) * 256;
        const int r = e >> 2, c = e & 3;
        const unsigned d = base + (j >> 1) * PL + (unsigned)(r * 80 + c * 16);
        const __nv_bfloat16* g;
        switch (j >> 1) {
            case 0:  g = g_Shi + (size_t)(row0 + r) * Nn + kb + c * 8; break;
            case 1:  g = g_Slo + (size_t)(row0 + r) * Nn + kb + c * 8; break;
            case 2:  g = Bhi   + (size_t)(col0 + r) * Nn + kb + c * 8; break;
            default: g = Blo   + (size_t)(col0 + r) * Nn + kb + c * 8; break;
        }
        cpa16(d, g);
    }
    asm volatile("cp.async.commit_group;");
}

template <int EPI>
__global__ void __launch_bounds__(256, 2) mma_gemm(const __nv_bfloat16* __restrict__ Bhi,
                                                   const __nv_bfloat16* __restrict__ Blo,
                                                   const float* __restrict__ Cin,
                                                   float* __restrict__ Yout) {
    extern __shared__ char smem[];
    const unsigned smb = smem_u32(smem);
    const int tid = threadIdx.x, wid = tid >> 5, lane = tid & 31;
    const int col0 = blockIdx.x * NT;
    const int row0 = blockIdx.y * MT;
    const int wm = (wid >> 1) * 32;
    const int wn = (wid & 1) * 64;

    float acc[2][8][4];
#pragma unroll
    for (int f = 0; f < 2; f++)
#pragma unroll
        for (int g = 0; g < 8; g++)
#pragma unroll
            for (int q = 0; q < 4; q++) acc[f][g][q] = 0.f;

    gemm_issue<EPI>(smb, tid, row0, col0, Bhi, Blo, 0);

    const int am = wm + (lane & 15);
    const int akb = ((lane >> 4) * 8) * 2;
    const int bn = wn + ((lane >> 4) << 3) + (lane & 7);
    const int bkb = (((lane >> 3) & 1) * 8) * 2;

    for (int i = 0; i < NKC; i++) {
        if (i + 1 < NKC) {
            gemm_issue<EPI>(smb, tid, row0, col0, Bhi, Blo, i + 1);
            asm volatile("cp.async.wait_group 1;");
        } else {
            asm volatile("cp.async.wait_group 0;");
        }
        __syncthreads();

        const unsigned base = smb + (unsigned)(i & 1) * STG;
#pragma unroll
        for (int ks = 0; ks < 2; ks++) {
            unsigned Ah[2][4], Al[2][4];
#pragma unroll
            for (int f = 0; f < 2; f++) {
                const unsigned ad = base + (unsigned)((am + f * 16) * 80 + akb + ks * 32);
                ldsm4(Ah[f], ad);
                ldsm4(Al[f], ad + PL);
            }
#pragma unroll
            for (int g4 = 0; g4 < 4; g4++) {
                unsigned Bh[4], Bl[4];
                const unsigned bd = base + 2 * PL +
                                    (unsigned)((bn + g4 * 16) * 80 + bkb + ks * 32);
                ldsm4(Bh, bd);
                ldsm4(Bl, bd + PL);
#pragma unroll
                for (int f = 0; f < 2; f++) {
#pragma unroll
                    for (int h = 0; h < 2; h++) {
                        float* c = acc[f][g4 * 2 + h];
                        mma_bf16(c, Ah[f], Bh + h * 2);
                        mma_bf16(c, Ah[f], Bl + h * 2);
                        mma_bf16(c, Al[f], Bh + h * 2);
                    }
                }
            }
        }
        __syncthreads();
    }

#pragma unroll
    for (int f = 0; f < 2; f++) {
#pragma unroll
        for (int g = 0; g < 8; g++) {
            const int m = row0 + wm + f * 16 + (lane >> 2);
            const int n = col0 + wn + g * 8 + (lane & 3) * 2;
            const float* c = acc[f][g];
            const size_t o0 = (size_t)m * BC + n;
            const size_t o1 = (size_t)(m + 8) * BC + n;
            if (EPI == 0) {
                *reinterpret_cast<float2*>(&Yout[o0]) = make_float2(c[0], c[1]);
                *reinterpret_cast<float2*>(&Yout[o1]) = make_float2(c[2], c[3]);
            } else {
                float2 x0 = *reinterpret_cast<const float2*>(&Cin[o0]);
                float2 x1 = *reinterpret_cast<const float2*>(&Cin[o1]);
                *reinterpret_cast<float2*>(&Yout[o0]) =
                    make_float2(2.f * c[0] - x0.x, 2.f * c[1] - x0.y);
                *reinterpret_cast<float2*>(&Yout[o1]) =
                    make_float2(2.f * c[2] - x1.x, 2.f * c[3] - x1.y);
            }
        }
    }
}

// ---------------------------------------------------------------------------
// K4: transpose-split Y1 -> Y1^T hi/lo bf16 planes (unchanged)
// ---------------------------------------------------------------------------
__global__ void __launch_bounds__(256) tsplit_kernel() {
    __shared__ float t[32][33];
    const int c0 = blockIdx.x * 32, n0 = blockIdx.y * 32;
    const int tx = threadIdx.x, ty = threadIdx.y;
#pragma unroll
    for (int j = 0; j < 32; j += 8)
        t[ty + j][tx] = g_Y1[(size_t)(n0 + ty + j) * BC + c0 + tx];
    __syncthreads();
#pragma unroll
    for (int j = 0; j < 32; j += 8) {
        float v = t[tx][ty + j];
        __nv_bfloat16 h = __float2bfloat16(v);
        size_t o = (size_t)(c0 + ty + j) * Nn + n0 + tx;
        g_Yth[o] = h;
        g_Ytl[o] = __float2bfloat16(v - __bfloat162float(h));
    }
}

// ---------------------------------------------------------------------------
// K5 (R13): projection — exact R7/R8 structure (1 node/block, 256 threads,
// same smem layout & occupancy); inner loops in packed fma.rn.f32x2 only.
// GATE: ZR = sigmoid(acc + bias);  else: out = r*st + (1-r)*tanh(acc + bias)
// ---------------------------------------------------------------------------
template <int O, bool GATE>
__global__ void __launch_bounds__(256) proj_kernel(const float* __restrict__ E,
                                                   const float* __restrict__ W,
                                                   const float* __restrict__ bp,
                                                   const float* __restrict__ st,
                                                   float* __restrict__ outp) {
    constexpr int OV = O / 4;
    constexpr int NBG = 256 / OV;
    constexpr int BPT = Bb / NBG;

    extern __shared__ float sm[];
    float* xg = sm;                  // [64][198]
    float* ws = sm + Bb * KC;        // [TKI][O]
    __shared__ float Esh[16];

    const int n = blockIdx.x, tid = threadIdx.x;
    const int to = tid % OV, tb = tid / OV;

    if (tid < 16) Esh[tid] = E[n * 16 + tid];

    const float* bufs[3] = {g_X0, g_Y1, g_Y2};
#pragma unroll
    for (int k = 0; k < 3; k++) {
        const float* src = bufs[k] + (size_t)n * BC;
        for (int e = tid; e < Bb * Cc; e += 256) {
            int b = e / Cc, i = e - b * Cc;
            xg[b * KC + k * Cc + i] = src[e];
        }
    }
    __syncthreads();

    unsigned long long acc[BPT][2];
#pragma unroll
    for (int j = 0; j < BPT; j++) { acc[j][0] = 0ull; acc[j][1] = 0ull; }

    for (int kt = 0; kt < KC; kt += TKI) {
        // build ws tile (FFMA2)
        for (int e = tid; e < TKI * OV; e += 256) {
            int kk = e / OV, o4 = e - kk * OV;
            const float* wp = W + (size_t)(kt + kk) * O + o4 * 4;
            unsigned long long s0 = 0ull, s1 = 0ull;
#pragma unroll
            for (int d = 0; d < 16; d++) {
                float4 w = *reinterpret_cast<const float4*>(wp + (size_t)d * KC * O);
                unsigned long long e2 = dup2(Esh[d]);
                unsigned long long w0 = packf2(w.x, w.y), w1 = packf2(w.z, w.w);
                ffma2(s0, e2, w0);
                ffma2(s1, e2, w1);
            }
            ulonglong2 ov;
            ov.x = s0;
            ov.y = s1;
            *reinterpret_cast<ulonglong2*>(&ws[kk * O + o4 * 4]) = ov;
        }
        __syncthreads();

        // micro-GEMM (FFMA2)
        for (int kk = 0; kk < TKI; kk++) {
            ulonglong2 wq = *reinterpret_cast<const ulonglong2*>(&ws[kk * O + to * 4]);
            float xv[BPT];
#pragma unroll
            for (int j = 0; j < BPT; j++) xv[j] = xg[(tb * BPT + j) * KC + kt + kk];
#pragma unroll
            for (int j = 0; j < BPT; j++) {
                unsigned long long xd = dup2(xv[j]);
                ffma2(acc[j][0], xd, wq.x);
                ffma2(acc[j][1], xd, wq.y);
            }
        }
        __syncthreads();
    }

    float bias[4];
#pragma unroll
    for (int jo = 0; jo < 4; jo++) {
        float s = 0.f;
#pragma unroll
        for (int d = 0; d < 16; d++) s += Esh[d] * bp[d * O + to * 4 + jo];
        bias[jo] = s;
    }

#pragma unroll
    for (int j = 0; j < BPT; j++) {
        const int b = tb * BPT + j;
        F2u u0, u1;
        u0.u = acc[j][0];
        u1.u = acc[j][1];
        float a0 = u0.f.x + bias[0], a1 = u0.f.y + bias[1];
        float a2 = u1.f.x + bias[2], a3 = u1.f.y + bias[3];
        if (GATE) {
            float4 o;
            o.x = 1.f / (1.f + expf(-a0));
            o.y = 1.f / (1.f + expf(-a1));
            o.z = 1.f / (1.f + expf(-a2));
            o.w = 1.f / (1.f + expf(-a3));
            *reinterpret_cast<float4*>(&g_ZR[((size_t)b * Nn + n) * OG + to * 4]) = o;
        } else {
            float av[4] = {a0, a1, a2, a3};
            float vals[4];
#pragma unroll
            for (int jo = 0; jo < 4; jo++) {
                int oo = to * 4 + jo;
                float hc = tanhf(av[jo]);
                float r = g_ZR[((size_t)b * Nn + n) * OG + Hh + oo];
                float sv = st[((size_t)b * Nn + n) * Hh + oo];
                vals[jo] = r * sv + (1.f - r) * hc;
            }
            float4 o = make_float4(vals[0], vals[1], vals[2], vals[3]);
            *reinterpret_cast<float4*>(&outp[((size_t)b * Nn + n) * Hh + to * 4]) = o;
        }
    }
}

// ---------------------------------------------------------------------------
extern "C" void kernel_launch(void* const* d_in, const int* in_sizes, int n_in,
                              void* d_out, int out_size) {
    const float* x    = (const float*)d_in[0];
    const float* st   = (const float*)d_in[1];
    const float* E    = (const float*)d_in[2];
    const float* mask = (const float*)d_in[3];
    const float* gW   = (const float*)d_in[4];
    const float* gb   = (const float*)d_in[5];
    const float* uW   = (const float*)d_in[6];
    const float* ub   = (const float*)d_in[7];
    const int*   normp = (const int*)d_in[8];
    float* outp = (float*)d_out;

    void *pX0, *pY1, *pY2, *pXth, *pXtl, *pYth, *pYtl;
    cudaGetSymbolAddress(&pX0, g_X0);
    cudaGetSymbolAddress(&pY1, g_Y1);
    cudaGetSymbolAddress(&pY2, g_Y2);
    cudaGetSymbolAddress(&pXth, g_Xth);
    cudaGetSymbolAddress(&pXtl, g_Xtl);
    cudaGetSymbolAddress(&pYth, g_Yth);
    cudaGetSymbolAddress(&pYtl, g_Ytl);

    const int smem_mma = 2 * STG;                                 // 81920
    cudaFuncSetAttribute(mma_gemm<0>, cudaFuncAttributeMaxDynamicSharedMemorySize, smem_mma);
    cudaFuncSetAttribute(mma_gemm<1>, cudaFuncAttributeMaxDynamicSharedMemorySize, smem_mma);

    const int smem_g = (Bb * KC + TKI * OG) * 4;                  // 67584
    const int smem_u = (Bb * KC + TKI * OU) * 4;                  // 59136
    cudaFuncSetAttribute(proj_kernel<OG, true>, cudaFuncAttributeMaxDynamicSharedMemorySize, smem_g);
    cudaFuncSetAttribute(proj_kernel<OU, false>, cudaFuncAttributeMaxDynamicSharedMemorySize, smem_u);

    dim3 gg(BC / NT, Nn / MT);                   // (33, 16)
    dim3 pg(Nn / 32, Bb);                        // (64, 64)
    dim3 tg(BC / 32, Nn / 32);                   // (132, 64)

    supports_kernel<<<Nn, 256>>>(E, mask, normp);

    // gate GCN
    pack_kernel<false><<<pg, 256>>>(x, st);
    mma_gemm<0><<<gg, 256, smem_mma>>>((const __nv_bfloat16*)pXth, (const __nv_bfloat16*)pXtl,
                                       nullptr, (float*)pY1);
    tsplit_kernel<<<tg, dim3(32, 8)>>>();
    mma_gemm<1><<<gg, 256, smem_mma>>>((const __nv_bfloat16*)pYth, (const __nv_bfloat16*)pYtl,
                                       (const float*)pX0, (float*)pY2);
    proj_kernel<OG, true><<<Nn, 256, smem_g>>>(E, gW, gb, nullptr, nullptr);

    // candidate GCN + GRU combine
    pack_kernel<true><<<pg, 256>>>(x, st);
    mma_gemm<0><<<gg, 256, smem_mma>>>((const __nv_bfloat16*)pXth, (const __nv_bfloat16*)pXtl,
                                       nullptr, (float*)pY1);
    tsplit_kernel<<<tg, dim3(32, 8)>>>();
    mma_gemm<1><<<gg, 256, smem_mma>>>((const __nv_bfloat16*)pYth, (const __nv_bfloat16*)pYtl,
                                       (const float*)pX0, (float*)pY2);
    proj_kernel<OU, false><<<Nn, 256, smem_u>>>(E, uW, ub, st, outp);
}

// round 15
// speedup vs baseline: 1.4323x; 1.1977x over previous
#include <cuda_runtime.h>
#include <cuda_fp16.h>
#include <math.h>

// ---------------------------------------------------------------------------
// AGCRN cell, B=64, N=2048, Din=2, H=64, K=3, D=16.
// R14: GEMMs switch bf16x3 -> fp16x2 (A=S single fp16 plane, B split hi/lo,
// 2 MMA products). 33% fewer HMMA ops. Proj/pack/supports structure = R13.
// ---------------------------------------------------------------------------

#define Nn 2048
#define Bb 64
#define Cc 66
#define BC 4224             // Bb * Cc = 33 * 128
#define KC 198              // 3 * Cc
#define OG 128
#define OU 64
#define Hh 64

#define MT 128              // GEMM m-tile (nodes)
#define NT 128              // GEMM n-tile (bc columns)
#define KT 32               // k per stage
#define NKC (Nn / KT)       // 64 stages
#define PL 10240            // bytes per smem plane: 128 rows * 80B
#define STG (3 * PL)        // 30720 bytes per stage: [A][Bhi][Blo]

#define TKI 33              // proj k-tile

// scratch (__device__ globals)
__device__ __half g_Shi[(size_t)Nn * Nn];   // S fp16 plane (k-major rows)
__device__ __half g_Xth[(size_t)BC * Nn];   // X^T hi (bc-major rows)
__device__ __half g_Xtl[(size_t)BC * Nn];
__device__ __half g_Yth[(size_t)BC * Nn];   // Y1^T hi
__device__ __half g_Ytl[(size_t)BC * Nn];
__device__ float g_X0[(size_t)Nn * BC];     // node-major fp32
__device__ float g_Y1[(size_t)Nn * BC];
__device__ float g_Y2[(size_t)Nn * BC];
__device__ float g_ZR[(size_t)Bb * Nn * OG];// gate out, [b][n][2H]

// ---------------------------------------------------------------------------
// PTX helpers (plain-sm_103-legal)
// ---------------------------------------------------------------------------
__device__ __forceinline__ unsigned smem_u32(const void* p) {
    unsigned a;
    asm("{ .reg .u64 t; cvta.to.shared.u64 t, %1; cvt.u32.u64 %0, t; }" : "=r"(a) : "l"(p));
    return a;
}
__device__ __forceinline__ void cpa16(unsigned dst, const void* src) {
    asm volatile("cp.async.cg.shared.global [%0], [%1], 16;" :: "r"(dst), "l"(src));
}
__device__ __forceinline__ void ldsm4(unsigned* r, unsigned a) {
    asm volatile("ldmatrix.sync.aligned.m8n8.x4.shared.b16 {%0,%1,%2,%3}, [%4];"
                 : "=r"(r[0]), "=r"(r[1]), "=r"(r[2]), "=r"(r[3]) : "r"(a));
}
__device__ __forceinline__ void mma_f16(float* c, const unsigned* a, const unsigned* b) {
    asm volatile(
        "mma.sync.aligned.m16n8k16.row.col.f32.f16.f16.f32 "
        "{%0,%1,%2,%3}, {%4,%5,%6,%7}, {%8,%9}, {%0,%1,%2,%3};"
        : "+f"(c[0]), "+f"(c[1]), "+f"(c[2]), "+f"(c[3])
        : "r"(a[0]), "r"(a[1]), "r"(a[2]), "r"(a[3]), "r"(b[0]), "r"(b[1]));
}
__device__ __forceinline__ void ffma2(unsigned long long& d, unsigned long long a,
                                      unsigned long long b) {
    asm("fma.rn.f32x2 %0, %1, %2, %0;" : "+l"(d) : "l"(a), "l"(b));
}
__device__ __forceinline__ unsigned long long dup2(float v) {
    unsigned long long r;
    unsigned u = __float_as_uint(v);
    asm("mov.b64 %0, {%1, %1};" : "=l"(r) : "r"(u));
    return r;
}
__device__ __forceinline__ unsigned long long packf2(float x, float y) {
    unsigned long long r;
    asm("mov.b64 %0, {%1, %2};" : "=l"(r) : "r"(__float_as_uint(x)), "r"(__float_as_uint(y)));
    return r;
}
union F2u { unsigned long long u; float2 f; };

// ---------------------------------------------------------------------------
// K1: supports (one block per row n)  -> single fp16 plane of S
// ---------------------------------------------------------------------------
__device__ __forceinline__ float block_reduce(float v, float* red, int tid, bool ismax) {
    red[tid] = v;
    __syncthreads();
    for (int s = 128; s > 0; s >>= 1) {
        if (tid < s) red[tid] = ismax ? fmaxf(red[tid], red[tid + s]) : (red[tid] + red[tid + s]);
        __syncthreads();
    }
    float r = red[0];
    __syncthreads();
    return r;
}

__global__ void __launch_bounds__(256) supports_kernel(const float* __restrict__ E,
                                                       const float* __restrict__ mask,
                                                       const int* __restrict__ normp) {
    __shared__ float row[Nn];
    __shared__ float red[256];
    const int n = blockIdx.x, tid = threadIdx.x;

    float En[16];
#pragma unroll
    for (int d = 0; d < 16; d++) En[d] = E[n * 16 + d];

    for (int m = tid; m < Nn; m += 256) {
        const float4* e4 = reinterpret_cast<const float4*>(E + m * 16);
        float v = 0.f;
#pragma unroll
        for (int q = 0; q < 4; q++) {
            float4 w = e4[q];
            v += En[4 * q + 0] * w.x + En[4 * q + 1] * w.y + En[4 * q + 2] * w.z + En[4 * q + 3] * w.w;
        }
        row[m] = fmaxf(v, 0.f);
    }
    __syncthreads();

    float lm = -1e30f;
    for (int m = tid; m < Nn; m += 256) lm = fmaxf(lm, row[m]);
    float mx = block_reduce(lm, red, tid, true);
    float ls = 0.f;
    for (int m = tid; m < Nn; m += 256) { float e = expf(row[m] - mx); row[m] = e; ls += e; }
    float sum = block_reduce(ls, red, tid, false);
    float inv = 1.f / sum;
    for (int m = tid; m < Nn; m += 256) row[m] = row[m] * inv * mask[(size_t)n * Nn + m];
    __syncthreads();

    if (*normp != 0) {
        lm = -1e30f;
        for (int m = tid; m < Nn; m += 256) lm = fmaxf(lm, row[m]);
        mx = block_reduce(lm, red, tid, true);
        ls = 0.f;
        for (int m = tid; m < Nn; m += 256) { float e = expf(row[m] - mx); row[m] = e; ls += e; }
        sum = block_reduce(ls, red, tid, false);
        inv = 1.f / sum;
        for (int m = tid; m < Nn; m += 256) row[m] *= inv;
        __syncthreads();
    }

    for (int m = tid; m < Nn; m += 256)
        g_Shi[(size_t)n * Nn + m] = __float2half(row[m]);
}

// ---------------------------------------------------------------------------
// K2: pack. Emits node-major fp32 X0 AND transposed fp16 hi/lo planes.
// grid (Nn/32, Bb), block 256.  CAND: concat(x, z*state), z = ZR[b][n][0:H]
// ---------------------------------------------------------------------------
template <bool CAND>
__global__ void __launch_bounds__(256) pack_kernel(const float* __restrict__ x,
                                                   const float* __restrict__ st) {
    __shared__ float s[32 * 65];
    __shared__ float z[32 * 65];
    __shared__ float xt[64];
    const int n0 = blockIdx.x * 32, b = blockIdx.y, tid = threadIdx.x;

    const float* sp = st + ((size_t)b * Nn + n0) * Hh;
#pragma unroll
    for (int j = 0; j < 8; j++) {
        int e = tid + 256 * j;
        s[(e >> 6) * 65 + (e & 63)] = sp[e];
    }
    if (tid < 64) xt[tid] = x[((size_t)b * Nn + n0 + (tid >> 1)) * 2 + (tid & 1)];
    if (CAND) {
        const float* zp = g_ZR + ((size_t)b * Nn + n0) * OG;
#pragma unroll
        for (int j = 0; j < 8; j++) {
            int e = tid + 256 * j;
            z[(e >> 6) * 65 + (e & 63)] = zp[(e >> 6) * OG + (e & 63)];
        }
    }
    __syncthreads();

    for (int e = tid; e < 32 * Cc; e += 256) {
        int i = e / Cc, c = e - i * Cc;
        float v = (c < 2) ? xt[i * 2 + c]
                          : (CAND ? z[i * 65 + (c - 2)] * s[i * 65 + (c - 2)]
                                  : s[i * 65 + (c - 2)]);
        g_X0[(size_t)(n0 + i) * BC + b * Cc + c] = v;
    }
    for (int e = tid; e < Cc * 32; e += 256) {
        int c = e >> 5, i = e & 31;
        float v = (c < 2) ? xt[i * 2 + c]
                          : (CAND ? z[i * 65 + (c - 2)] * s[i * 65 + (c - 2)]
                                  : s[i * 65 + (c - 2)]);
        __half h = __float2half(v);
        size_t o = (size_t)(b * Cc + c) * Nn + n0 + i;
        g_Xth[o] = h;
        g_Xtl[o] = __float2half(v - __half2float(h));
    }
}

// ---------------------------------------------------------------------------
// K3: warp-mma GEMM, fp16x2.  Y = S @ B-planes
//   (EPI=0: Y1 = acc;  EPI=1: Y2 = 2*acc - C)
// smem per stage: [A][Bhi][Blo], each 128 rows x 80B.
// ---------------------------------------------------------------------------
template <int EPI>
__device__ __forceinline__ void gemm_issue(unsigned smb, int tid, int row0, int col0,
                                           const __half* __restrict__ Bhi,
                                           const __half* __restrict__ Blo, int ch) {
    const unsigned base = smb + (unsigned)(ch & 1) * STG;
    const size_t kb = (size_t)ch * KT;
#pragma unroll
    for (int j = 0; j < 6; j++) {
        const int e = tid + (j & 1) * 256;
        const int r = e >> 2, c = e & 3;
        const unsigned d = base + (j >> 1) * PL + (unsigned)(r * 80 + c * 16);
        const __half* g;
        switch (j >> 1) {
            case 0:  g = g_Shi + (size_t)(row0 + r) * Nn + kb + c * 8; break;
            case 1:  g = Bhi   + (size_t)(col0 + r) * Nn + kb + c * 8; break;
            default: g = Blo   + (size_t)(col0 + r) * Nn + kb + c * 8; break;
        }
        cpa16(d, g);
    }
    asm volatile("cp.async.commit_group;");
}

template <int EPI>
__global__ void __launch_bounds__(256, 2) mma_gemm(const __half* __restrict__ Bhi,
                                                   const __half* __restrict__ Blo,
                                                   const float* __restrict__ Cin,
                                                   float* __restrict__ Yout) {
    extern __shared__ char smem[];
    const unsigned smb = smem_u32(smem);
    const int tid = threadIdx.x, wid = tid >> 5, lane = tid & 31;
    const int col0 = blockIdx.x * NT;
    const int row0 = blockIdx.y * MT;
    const int wm = (wid >> 1) * 32;
    const int wn = (wid & 1) * 64;

    float acc[2][8][4];
#pragma unroll
    for (int f = 0; f < 2; f++)
#pragma unroll
        for (int g = 0; g < 8; g++)
#pragma unroll
            for (int q = 0; q < 4; q++) acc[f][g][q] = 0.f;

    gemm_issue<EPI>(smb, tid, row0, col0, Bhi, Blo, 0);

    const int am = wm + (lane & 15);
    const int akb = ((lane >> 4) * 8) * 2;
    const int bn = wn + ((lane >> 4) << 3) + (lane & 7);
    const int bkb = (((lane >> 3) & 1) * 8) * 2;

    for (int i = 0; i < NKC; i++) {
        if (i + 1 < NKC) {
            gemm_issue<EPI>(smb, tid, row0, col0, Bhi, Blo, i + 1);
            asm volatile("cp.async.wait_group 1;");
        } else {
            asm volatile("cp.async.wait_group 0;");
        }
        __syncthreads();

        const unsigned base = smb + (unsigned)(i & 1) * STG;
#pragma unroll
        for (int ks = 0; ks < 2; ks++) {
            unsigned Ah[2][4];
#pragma unroll
            for (int f = 0; f < 2; f++)
                ldsm4(Ah[f], base + (unsigned)((am + f * 16) * 80 + akb + ks * 32));
#pragma unroll
            for (int g4 = 0; g4 < 4; g4++) {
                unsigned Bh[4], Bl[4];
                const unsigned bd = base + PL +
                                    (unsigned)((bn + g4 * 16) * 80 + bkb + ks * 32);
                ldsm4(Bh, bd);
                ldsm4(Bl, bd + PL);
#pragma unroll
                for (int f = 0; f < 2; f++) {
#pragma unroll
                    for (int h = 0; h < 2; h++) {
                        float* c = acc[f][g4 * 2 + h];
                        mma_f16(c, Ah[f], Bh + h * 2);
                        mma_f16(c, Ah[f], Bl + h * 2);
                    }
                }
            }
        }
        __syncthreads();
    }

#pragma unroll
    for (int f = 0; f < 2; f++) {
#pragma unroll
        for (int g = 0; g < 8; g++) {
            const int m = row0 + wm + f * 16 + (lane >> 2);
            const int n = col0 + wn + g * 8 + (lane & 3) * 2;
            const float* c = acc[f][g];
            const size_t o0 = (size_t)m * BC + n;
            const size_t o1 = (size_t)(m + 8) * BC + n;
            if (EPI == 0) {
                *reinterpret_cast<float2*>(&Yout[o0]) = make_float2(c[0], c[1]);
                *reinterpret_cast<float2*>(&Yout[o1]) = make_float2(c[2], c[3]);
            } else {
                float2 x0 = *reinterpret_cast<const float2*>(&Cin[o0]);
                float2 x1 = *reinterpret_cast<const float2*>(&Cin[o1]);
                *reinterpret_cast<float2*>(&Yout[o0]) =
                    make_float2(2.f * c[0] - x0.x, 2.f * c[1] - x0.y);
                *reinterpret_cast<float2*>(&Yout[o1]) =
                    make_float2(2.f * c[2] - x1.x, 2.f * c[3] - x1.y);
            }
        }
    }
}

// ---------------------------------------------------------------------------
// K4: transpose-split Y1 -> Y1^T hi/lo fp16 planes
// ---------------------------------------------------------------------------
__global__ void __launch_bounds__(256) tsplit_kernel() {
    __shared__ float t[32][33];
    const int c0 = blockIdx.x * 32, n0 = blockIdx.y * 32;
    const int tx = threadIdx.x, ty = threadIdx.y;
#pragma unroll
    for (int j = 0; j < 32; j += 8)
        t[ty + j][tx] = g_Y1[(size_t)(n0 + ty + j) * BC + c0 + tx];
    __syncthreads();
#pragma unroll
    for (int j = 0; j < 32; j += 8) {
        float v = t[tx][ty + j];
        __half h = __float2half(v);
        size_t o = (size_t)(c0 + ty + j) * Nn + n0 + tx;
        g_Yth[o] = h;
        g_Ytl[o] = __float2half(v - __half2float(h));
    }
}

// ---------------------------------------------------------------------------
// K5: projection — R13 structure (1 node/block, 256 threads, FFMA2 loops)
// GATE: ZR = sigmoid(acc + bias);  else: out = r*st + (1-r)*tanh(acc + bias)
// ---------------------------------------------------------------------------
template <int O, bool GATE>
__global__ void __launch_bounds__(256) proj_kernel(const float* __restrict__ E,
                                                   const float* __restrict__ W,
                                                   const float* __restrict__ bp,
                                                   const float* __restrict__ st,
                                                   float* __restrict__ outp) {
    constexpr int OV = O / 4;
    constexpr int NBG = 256 / OV;
    constexpr int BPT = Bb / NBG;

    extern __shared__ float sm[];
    float* xg = sm;                  // [64][198]
    float* ws = sm + Bb * KC;        // [TKI][O]
    __shared__ float Esh[16];

    const int n = blockIdx.x, tid = threadIdx.x;
    const int to = tid % OV, tb = tid / OV;

    if (tid < 16) Esh[tid] = E[n * 16 + tid];

    const float* bufs[3] = {g_X0, g_Y1, g_Y2};
#pragma unroll
    for (int k = 0; k < 3; k++) {
        const float* src = bufs[k] + (size_t)n * BC;
        for (int e = tid; e < Bb * Cc; e += 256) {
            int b = e / Cc, i = e - b * Cc;
            xg[b * KC + k * Cc + i] = src[e];
        }
    }
    __syncthreads();

    unsigned long long acc[BPT][2];
#pragma unroll
    for (int j = 0; j < BPT; j++) { acc[j][0] = 0ull; acc[j][1] = 0ull; }

    for (int kt = 0; kt < KC; kt += TKI) {
        // build ws tile (FFMA2)
        for (int e = tid; e < TKI * OV; e += 256) {
            int kk = e / OV, o4 = e - kk * OV;
            const float* wp = W + (size_t)(kt + kk) * O + o4 * 4;
            unsigned long long s0 = 0ull, s1 = 0ull;
#pragma unroll
            for (int d = 0; d < 16; d++) {
                float4 w = *reinterpret_cast<const float4*>(wp + (size_t)d * KC * O);
                unsigned long long e2 = dup2(Esh[d]);
                unsigned long long w0 = packf2(w.x, w.y), w1 = packf2(w.z, w.w);
                ffma2(s0, e2, w0);
                ffma2(s1, e2, w1);
            }
            ulonglong2 ov;
            ov.x = s0;
            ov.y = s1;
            *reinterpret_cast<ulonglong2*>(&ws[kk * O + o4 * 4]) = ov;
        }
        __syncthreads();

        // micro-GEMM (FFMA2)
        for (int kk = 0; kk < TKI; kk++) {
            ulonglong2 wq = *reinterpret_cast<const ulonglong2*>(&ws[kk * O + to * 4]);
            float xv[BPT];
#pragma unroll
            for (int j = 0; j < BPT; j++) xv[j] = xg[(tb * BPT + j) * KC + kt + kk];
#pragma unroll
            for (int j = 0; j < BPT; j++) {
                unsigned long long xd = dup2(xv[j]);
                ffma2(acc[j][0], xd, wq.x);
                ffma2(acc[j][1], xd, wq.y);
            }
        }
        __syncthreads();
    }

    float bias[4];
#pragma unroll
    for (int jo = 0; jo < 4; jo++) {
        float s = 0.f;
#pragma unroll
        for (int d = 0; d < 16; d++) s += Esh[d] * bp[d * O + to * 4 + jo];
        bias[jo] = s;
    }

#pragma unroll
    for (int j = 0; j < BPT; j++) {
        const int b = tb * BPT + j;
        F2u u0, u1;
        u0.u = acc[j][0];
        u1.u = acc[j][1];
        float a0 = u0.f.x + bias[0], a1 = u0.f.y + bias[1];
        float a2 = u1.f.x + bias[2], a3 = u1.f.y + bias[3];
        if (GATE) {
            float4 o;
            o.x = 1.f / (1.f + expf(-a0));
            o.y = 1.f / (1.f + expf(-a1));
            o.z = 1.f / (1.f + expf(-a2));
            o.w = 1.f / (1.f + expf(-a3));
            *reinterpret_cast<float4*>(&g_ZR[((size_t)b * Nn + n) * OG + to * 4]) = o;
        } else {
            float av[4] = {a0, a1, a2, a3};
            float vals[4];
#pragma unroll
            for (int jo = 0; jo < 4; jo++) {
                int oo = to * 4 + jo;
                float hc = tanhf(av[jo]);
                float r = g_ZR[((size_t)b * Nn + n) * OG + Hh + oo];
                float sv = st[((size_t)b * Nn + n) * Hh + oo];
                vals[jo] = r * sv + (1.f - r) * hc;
            }
            float4 o = make_float4(vals[0], vals[1], vals[2], vals[3]);
            *reinterpret_cast<float4*>(&outp[((size_t)b * Nn + n) * Hh + to * 4]) = o;
        }
    }
}

// ---------------------------------------------------------------------------
extern "C" void kernel_launch(void* const* d_in, const int* in_sizes, int n_in,
                              void* d_out, int out_size) {
    const float* x    = (const float*)d_in[0];
    const float* st   = (const float*)d_in[1];
    const float* E    = (const float*)d_in[2];
    const float* mask = (const float*)d_in[3];
    const float* gW   = (const float*)d_in[4];
    const float* gb   = (const float*)d_in[5];
    const float* uW   = (const float*)d_in[6];
    const float* ub   = (const float*)d_in[7];
    const int*   normp = (const int*)d_in[8];
    float* outp = (float*)d_out;

    void *pX0, *pY1, *pY2, *pXth, *pXtl, *pYth, *pYtl;
    cudaGetSymbolAddress(&pX0, g_X0);
    cudaGetSymbolAddress(&pY1, g_Y1);
    cudaGetSymbolAddress(&pY2, g_Y2);
    cudaGetSymbolAddress(&pXth, g_Xth);
    cudaGetSymbolAddress(&pXtl, g_Xtl);
    cudaGetSymbolAddress(&pYth, g_Yth);
    cudaGetSymbolAddress(&pYtl, g_Ytl);

    const int smem_mma = 2 * STG;                                 // 61440
    cudaFuncSetAttribute(mma_gemm<0>, cudaFuncAttributeMaxDynamicSharedMemorySize, smem_mma);
    cudaFuncSetAttribute(mma_gemm<1>, cudaFuncAttributeMaxDynamicSharedMemorySize, smem_mma);

    const int smem_g = (Bb * KC + TKI * OG) * 4;                  // 67584
    const int smem_u = (Bb * KC + TKI * OU) * 4;                  // 59136
    cudaFuncSetAttribute(proj_kernel<OG, true>, cudaFuncAttributeMaxDynamicSharedMemorySize, smem_g);
    cudaFuncSetAttribute(proj_kernel<OU, false>, cudaFuncAttributeMaxDynamicSharedMemorySize, smem_u);

    dim3 gg(BC / NT, Nn / MT);                   // (33, 16)
    dim3 pg(Nn / 32, Bb);                        // (64, 64)
    dim3 tg(BC / 32, Nn / 32);                   // (132, 64)

    supports_kernel<<<Nn, 256>>>(E, mask, normp);

    // gate GCN
    pack_kernel<false><<<pg, 256>>>(x, st);
    mma_gemm<0><<<gg, 256, smem_mma>>>((const __half*)pXth, (const __half*)pXtl,
                                       nullptr, (float*)pY1);
    tsplit_kernel<<<tg, dim3(32, 8)>>>();
    mma_gemm<1><<<gg, 256, smem_mma>>>((const __half*)pYth, (const __half*)pYtl,
                                       (const float*)pX0, (float*)pY2);
    proj_kernel<OG, true><<<Nn, 256, smem_g>>>(E, gW, gb, nullptr, nullptr);

    // candidate GCN + GRU combine
    pack_kernel<true><<<pg, 256>>>(x, st);
    mma_gemm<0><<<gg, 256, smem_mma>>>((const __half*)pXth, (const __half*)pXtl,
                                       nullptr, (float*)pY1);
    tsplit_kernel<<<tg, dim3(32, 8)>>>();
    mma_gemm<1><<<gg, 256, smem_mma>>>((const __half*)pYth, (const __half*)pYtl,
                                       (const float*)pX0, (float*)pY2);
    proj_kernel<OU, false><<<Nn, 256, smem_u>>>(E, uW, ub, st, outp);
}

// round 16
// speedup vs baseline: 1.9407x; 1.3549x over previous
#include <cuda_runtime.h>
#include <cuda_fp16.h>
#include <math.h>

// ---------------------------------------------------------------------------
// AGCRN cell, B=64, N=2048, Din=2, H=64, K=3, D=16.
// R15: GEMMs pure fp16 (single plane A and B, 1 MMA product), fp32 accum.
// Calibrated error model: rel_err ~ 3.6e-4 (quadrature of A+B fp16 rounding).
// Proj/pack/supports structure unchanged from the 1636us kernel.
// ---------------------------------------------------------------------------

#define Nn 2048
#define Bb 64
#define Cc 66
#define BC 4224             // Bb * Cc = 33 * 128
#define KC 198              // 3 * Cc
#define OG 128
#define OU 64
#define Hh 64

#define MT 128              // GEMM m-tile (nodes)
#define NT 128              // GEMM n-tile (bc columns)
#define KT 32               // k per stage
#define NKC (Nn / KT)       // 64 stages
#define PL 10240            // bytes per smem plane: 128 rows * 80B
#define STG (2 * PL)        // 20480 bytes per stage: [A][B]

#define TKI 33              // proj k-tile

// scratch (__device__ globals)
__device__ __half g_Shi[(size_t)Nn * Nn];   // S fp16 plane (k-major rows)
__device__ __half g_Xth[(size_t)BC * Nn];   // X^T fp16 (bc-major rows)
__device__ __half g_Yth[(size_t)BC * Nn];   // Y1^T fp16
__device__ float g_X0[(size_t)Nn * BC];     // node-major fp32
__device__ float g_Y1[(size_t)Nn * BC];
__device__ float g_Y2[(size_t)Nn * BC];
__device__ float g_ZR[(size_t)Bb * Nn * OG];// gate out, [b][n][2H]

// ---------------------------------------------------------------------------
// PTX helpers (plain-sm_103-legal)
// ---------------------------------------------------------------------------
__device__ __forceinline__ unsigned smem_u32(const void* p) {
    unsigned a;
    asm("{ .reg .u64 t; cvta.to.shared.u64 t, %1; cvt.u32.u64 %0, t; }" : "=r"(a) : "l"(p));
    return a;
}
__device__ __forceinline__ void cpa16(unsigned dst, const void* src) {
    asm volatile("cp.async.cg.shared.global [%0], [%1], 16;" :: "r"(dst), "l"(src));
}
__device__ __forceinline__ void ldsm4(unsigned* r, unsigned a) {
    asm volatile("ldmatrix.sync.aligned.m8n8.x4.shared.b16 {%0,%1,%2,%3}, [%4];"
                 : "=r"(r[0]), "=r"(r[1]), "=r"(r[2]), "=r"(r[3]) : "r"(a));
}
__device__ __forceinline__ void mma_f16(float* c, const unsigned* a, const unsigned* b) {
    asm volatile(
        "mma.sync.aligned.m16n8k16.row.col.f32.f16.f16.f32 "
        "{%0,%1,%2,%3}, {%4,%5,%6,%7}, {%8,%9}, {%0,%1,%2,%3};"
        : "+f"(c[0]), "+f"(c[1]), "+f"(c[2]), "+f"(c[3])
        : "r"(a[0]), "r"(a[1]), "r"(a[2]), "r"(a[3]), "r"(b[0]), "r"(b[1]));
}
__device__ __forceinline__ void ffma2(unsigned long long& d, unsigned long long a,
                                      unsigned long long b) {
    asm("fma.rn.f32x2 %0, %1, %2, %0;" : "+l"(d) : "l"(a), "l"(b));
}
__device__ __forceinline__ unsigned long long dup2(float v) {
    unsigned long long r;
    unsigned u = __float_as_uint(v);
    asm("mov.b64 %0, {%1, %1};" : "=l"(r) : "r"(u));
    return r;
}
__device__ __forceinline__ unsigned long long packf2(float x, float y) {
    unsigned long long r;
    asm("mov.b64 %0, {%1, %2};" : "=l"(r) : "r"(__float_as_uint(x)), "r"(__float_as_uint(y)));
    return r;
}
union F2u { unsigned long long u; float2 f; };

// ---------------------------------------------------------------------------
// K1: supports (one block per row n)  -> single fp16 plane of S
// ---------------------------------------------------------------------------
__device__ __forceinline__ float block_reduce(float v, float* red, int tid, bool ismax) {
    red[tid] = v;
    __syncthreads();
    for (int s = 128; s > 0; s >>= 1) {
        if (tid < s) red[tid] = ismax ? fmaxf(red[tid], red[tid + s]) : (red[tid] + red[tid + s]);
        __syncthreads();
    }
    float r = red[0];
    __syncthreads();
    return r;
}

__global__ void __launch_bounds__(256) supports_kernel(const float* __restrict__ E,
                                                       const float* __restrict__ mask,
                                                       const int* __restrict__ normp) {
    __shared__ float row[Nn];
    __shared__ float red[256];
    const int n = blockIdx.x, tid = threadIdx.x;

    float En[16];
#pragma unroll
    for (int d = 0; d < 16; d++) En[d] = E[n * 16 + d];

    for (int m = tid; m < Nn; m += 256) {
        const float4* e4 = reinterpret_cast<const float4*>(E + m * 16);
        float v = 0.f;
#pragma unroll
        for (int q = 0; q < 4; q++) {
            float4 w = e4[q];
            v += En[4 * q + 0] * w.x + En[4 * q + 1] * w.y + En[4 * q + 2] * w.z + En[4 * q + 3] * w.w;
        }
        row[m] = fmaxf(v, 0.f);
    }
    __syncthreads();

    float lm = -1e30f;
    for (int m = tid; m < Nn; m += 256) lm = fmaxf(lm, row[m]);
    float mx = block_reduce(lm, red, tid, true);
    float ls = 0.f;
    for (int m = tid; m < Nn; m += 256) { float e = expf(row[m] - mx); row[m] = e; ls += e; }
    float sum = block_reduce(ls, red, tid, false);
    float inv = 1.f / sum;
    for (int m = tid; m < Nn; m += 256) row[m] = row[m] * inv * mask[(size_t)n * Nn + m];
    __syncthreads();

    if (*normp != 0) {
        lm = -1e30f;
        for (int m = tid; m < Nn; m += 256) lm = fmaxf(lm, row[m]);
        mx = block_reduce(lm, red, tid, true);
        ls = 0.f;
        for (int m = tid; m < Nn; m += 256) { float e = expf(row[m] - mx); row[m] = e; ls += e; }
        sum = block_reduce(ls, red, tid, false);
        inv = 1.f / sum;
        for (int m = tid; m < Nn; m += 256) row[m] *= inv;
        __syncthreads();
    }

    for (int m = tid; m < Nn; m += 256)
        g_Shi[(size_t)n * Nn + m] = __float2half(row[m]);
}

// ---------------------------------------------------------------------------
// K2: pack. Emits node-major fp32 X0 AND transposed fp16 plane.
// grid (Nn/32, Bb), block 256.  CAND: concat(x, z*state), z = ZR[b][n][0:H]
// ---------------------------------------------------------------------------
template <bool CAND>
__global__ void __launch_bounds__(256) pack_kernel(const float* __restrict__ x,
                                                   const float* __restrict__ st) {
    __shared__ float s[32 * 65];
    __shared__ float z[32 * 65];
    __shared__ float xt[64];
    const int n0 = blockIdx.x * 32, b = blockIdx.y, tid = threadIdx.x;

    const float* sp = st + ((size_t)b * Nn + n0) * Hh;
#pragma unroll
    for (int j = 0; j < 8; j++) {
        int e = tid + 256 * j;
        s[(e >> 6) * 65 + (e & 63)] = sp[e];
    }
    if (tid < 64) xt[tid] = x[((size_t)b * Nn + n0 + (tid >> 1)) * 2 + (tid & 1)];
    if (CAND) {
        const float* zp = g_ZR + ((size_t)b * Nn + n0) * OG;
#pragma unroll
        for (int j = 0; j < 8; j++) {
            int e = tid + 256 * j;
            z[(e >> 6) * 65 + (e & 63)] = zp[(e >> 6) * OG + (e & 63)];
        }
    }
    __syncthreads();

    for (int e = tid; e < 32 * Cc; e += 256) {
        int i = e / Cc, c = e - i * Cc;
        float v = (c < 2) ? xt[i * 2 + c]
                          : (CAND ? z[i * 65 + (c - 2)] * s[i * 65 + (c - 2)]
                                  : s[i * 65 + (c - 2)]);
        g_X0[(size_t)(n0 + i) * BC + b * Cc + c] = v;
    }
    for (int e = tid; e < Cc * 32; e += 256) {
        int c = e >> 5, i = e & 31;
        float v = (c < 2) ? xt[i * 2 + c]
                          : (CAND ? z[i * 65 + (c - 2)] * s[i * 65 + (c - 2)]
                                  : s[i * 65 + (c - 2)]);
        g_Xth[(size_t)(b * Cc + c) * Nn + n0 + i] = __float2half(v);
    }
}

// ---------------------------------------------------------------------------
// K3: warp-mma GEMM, pure fp16.  Y = S @ B
//   (EPI=0: Y1 = acc;  EPI=1: Y2 = 2*acc - C)
// smem per stage: [A][B], each 128 rows x 80B.
// ---------------------------------------------------------------------------
template <int EPI>
__device__ __forceinline__ void gemm_issue(unsigned smb, int tid, int row0, int col0,
                                           const __half* __restrict__ Bp, int ch) {
    const unsigned base = smb + (unsigned)(ch & 1) * STG;
    const size_t kb = (size_t)ch * KT;
#pragma unroll
    for (int j = 0; j < 4; j++) {
        const int e = tid + (j & 1) * 256;
        const int r = e >> 2, c = e & 3;
        const unsigned d = base + (j >> 1) * PL + (unsigned)(r * 80 + c * 16);
        const __half* g = (j >> 1) ? (Bp + (size_t)(col0 + r) * Nn + kb + c * 8)
                                   : (g_Shi + (size_t)(row0 + r) * Nn + kb + c * 8);
        cpa16(d, g);
    }
    asm volatile("cp.async.commit_group;");
}

template <int EPI>
__global__ void __launch_bounds__(256, 2) mma_gemm(const __half* __restrict__ Bp,
                                                   const float* __restrict__ Cin,
                                                   float* __restrict__ Yout) {
    extern __shared__ char smem[];
    const unsigned smb = smem_u32(smem);
    const int tid = threadIdx.x, wid = tid >> 5, lane = tid & 31;
    const int col0 = blockIdx.x * NT;
    const int row0 = blockIdx.y * MT;
    const int wm = (wid >> 1) * 32;
    const int wn = (wid & 1) * 64;

    float acc[2][8][4];
#pragma unroll
    for (int f = 0; f < 2; f++)
#pragma unroll
        for (int g = 0; g < 8; g++)
#pragma unroll
            for (int q = 0; q < 4; q++) acc[f][g][q] = 0.f;

    gemm_issue<EPI>(smb, tid, row0, col0, Bp, 0);

    const int am = wm + (lane & 15);
    const int akb = ((lane >> 4) * 8) * 2;
    const int bn = wn + ((lane >> 4) << 3) + (lane & 7);
    const int bkb = (((lane >> 3) & 1) * 8) * 2;

    for (int i = 0; i < NKC; i++) {
        if (i + 1 < NKC) {
            gemm_issue<EPI>(smb, tid, row0, col0, Bp, i + 1);
            asm volatile("cp.async.wait_group 1;");
        } else {
            asm volatile("cp.async.wait_group 0;");
        }
        __syncthreads();

        const unsigned base = smb + (unsigned)(i & 1) * STG;
#pragma unroll
        for (int ks = 0; ks < 2; ks++) {
            unsigned Ah[2][4];
#pragma unroll
            for (int f = 0; f < 2; f++)
                ldsm4(Ah[f], base + (unsigned)((am + f * 16) * 80 + akb + ks * 32));
#pragma unroll
            for (int g4 = 0; g4 < 4; g4++) {
                unsigned Bh[4];
                ldsm4(Bh, base + PL + (unsigned)((bn + g4 * 16) * 80 + bkb + ks * 32));
#pragma unroll
                for (int f = 0; f < 2; f++) {
#pragma unroll
                    for (int h = 0; h < 2; h++)
                        mma_f16(acc[f][g4 * 2 + h], Ah[f], Bh + h * 2);
                }
            }
        }
        __syncthreads();
    }

#pragma unroll
    for (int f = 0; f < 2; f++) {
#pragma unroll
        for (int g = 0; g < 8; g++) {
            const int m = row0 + wm + f * 16 + (lane >> 2);
            const int n = col0 + wn + g * 8 + (lane & 3) * 2;
            const float* c = acc[f][g];
            const size_t o0 = (size_t)m * BC + n;
            const size_t o1 = (size_t)(m + 8) * BC + n;
            if (EPI == 0) {
                *reinterpret_cast<float2*>(&Yout[o0]) = make_float2(c[0], c[1]);
                *reinterpret_cast<float2*>(&Yout[o1]) = make_float2(c[2], c[3]);
            } else {
                float2 x0 = *reinterpret_cast<const float2*>(&Cin[o0]);
                float2 x1 = *reinterpret_cast<const float2*>(&Cin[o1]);
                *reinterpret_cast<float2*>(&Yout[o0]) =
                    make_float2(2.f * c[0] - x0.x, 2.f * c[1] - x0.y);
                *reinterpret_cast<float2*>(&Yout[o1]) =
                    make_float2(2.f * c[2] - x1.x, 2.f * c[3] - x1.y);
            }
        }
    }
}

// ---------------------------------------------------------------------------
// K4: transpose-split Y1 -> Y1^T fp16 plane
// ---------------------------------------------------------------------------
__global__ void __launch_bounds__(256) tsplit_kernel() {
    __shared__ float t[32][33];
    const int c0 = blockIdx.x * 32, n0 = blockIdx.y * 32;
    const int tx = threadIdx.x, ty = threadIdx.y;
#pragma unroll
    for (int j = 0; j < 32; j += 8)
        t[ty + j][tx] = g_Y1[(size_t)(n0 + ty + j) * BC + c0 + tx];
    __syncthreads();
#pragma unroll
    for (int j = 0; j < 32; j += 8)
        g_Yth[(size_t)(c0 + ty + j) * Nn + n0 + tx] = __float2half(t[tx][ty + j]);
}

// ---------------------------------------------------------------------------
// K5: projection — unchanged (1 node/block, 256 threads, FFMA2 loops)
// GATE: ZR = sigmoid(acc + bias);  else: out = r*st + (1-r)*tanh(acc + bias)
// ---------------------------------------------------------------------------
template <int O, bool GATE>
__global__ void __launch_bounds__(256) proj_kernel(const float* __restrict__ E,
                                                   const float* __restrict__ W,
                                                   const float* __restrict__ bp,
                                                   const float* __restrict__ st,
                                                   float* __restrict__ outp) {
    constexpr int OV = O / 4;
    constexpr int NBG = 256 / OV;
    constexpr int BPT = Bb / NBG;

    extern __shared__ float sm[];
    float* xg = sm;                  // [64][198]
    float* ws = sm + Bb * KC;        // [TKI][O]
    __shared__ float Esh[16];

    const int n = blockIdx.x, tid = threadIdx.x;
    const int to = tid % OV, tb = tid / OV;

    if (tid < 16) Esh[tid] = E[n * 16 + tid];

    const float* bufs[3] = {g_X0, g_Y1, g_Y2};
#pragma unroll
    for (int k = 0; k < 3; k++) {
        const float* src = bufs[k] + (size_t)n * BC;
        for (int e = tid; e < Bb * Cc; e += 256) {
            int b = e / Cc, i = e - b * Cc;
            xg[b * KC + k * Cc + i] = src[e];
        }
    }
    __syncthreads();

    unsigned long long acc[BPT][2];
#pragma unroll
    for (int j = 0; j < BPT; j++) { acc[j][0] = 0ull; acc[j][1] = 0ull; }

    for (int kt = 0; kt < KC; kt += TKI) {
        // build ws tile (FFMA2)
        for (int e = tid; e < TKI * OV; e += 256) {
            int kk = e / OV, o4 = e - kk * OV;
            const float* wp = W + (size_t)(kt + kk) * O + o4 * 4;
            unsigned long long s0 = 0ull, s1 = 0ull;
#pragma unroll
            for (int d = 0; d < 16; d++) {
                float4 w = *reinterpret_cast<const float4*>(wp + (size_t)d * KC * O);
                unsigned long long e2 = dup2(Esh[d]);
                unsigned long long w0 = packf2(w.x, w.y), w1 = packf2(w.z, w.w);
                ffma2(s0, e2, w0);
                ffma2(s1, e2, w1);
            }
            ulonglong2 ov;
            ov.x = s0;
            ov.y = s1;
            *reinterpret_cast<ulonglong2*>(&ws[kk * O + o4 * 4]) = ov;
        }
        __syncthreads();

        // micro-GEMM (FFMA2)
        for (int kk = 0; kk < TKI; kk++) {
            ulonglong2 wq = *reinterpret_cast<const ulonglong2*>(&ws[kk * O + to * 4]);
            float xv[BPT];
#pragma unroll
            for (int j = 0; j < BPT; j++) xv[j] = xg[(tb * BPT + j) * KC + kt + kk];
#pragma unroll
            for (int j = 0; j < BPT; j++) {
                unsigned long long xd = dup2(xv[j]);
                ffma2(acc[j][0], xd, wq.x);
                ffma2(acc[j][1], xd, wq.y);
            }
        }
        __syncthreads();
    }

    float bias[4];
#pragma unroll
    for (int jo = 0; jo < 4; jo++) {
        float s = 0.f;
#pragma unroll
        for (int d = 0; d < 16; d++) s += Esh[d] * bp[d * O + to * 4 + jo];
        bias[jo] = s;
    }

#pragma unroll
    for (int j = 0; j < BPT; j++) {
        const int b = tb * BPT + j;
        F2u u0, u1;
        u0.u = acc[j][0];
        u1.u = acc[j][1];
        float a0 = u0.f.x + bias[0], a1 = u0.f.y + bias[1];
        float a2 = u1.f.x + bias[2], a3 = u1.f.y + bias[3];
        if (GATE) {
            float4 o;
            o.x = 1.f / (1.f + expf(-a0));
            o.y = 1.f / (1.f + expf(-a1));
            o.z = 1.f / (1.f + expf(-a2));
            o.w = 1.f / (1.f + expf(-a3));
            *reinterpret_cast<float4*>(&g_ZR[((size_t)b * Nn + n) * OG + to * 4]) = o;
        } else {
            float av[4] = {a0, a1, a2, a3};
            float vals[4];
#pragma unroll
            for (int jo = 0; jo < 4; jo++) {
                int oo = to * 4 + jo;
                float hc = tanhf(av[jo]);
                float r = g_ZR[((size_t)b * Nn + n) * OG + Hh + oo];
                float sv = st[((size_t)b * Nn + n) * Hh + oo];
                vals[jo] = r * sv + (1.f - r) * hc;
            }
            float4 o = make_float4(vals[0], vals[1], vals[2], vals[3]);
            *reinterpret_cast<float4*>(&outp[((size_t)b * Nn + n) * Hh + to * 4]) = o;
        }
    }
}

// ---------------------------------------------------------------------------
extern "C" void kernel_launch(void* const* d_in, const int* in_sizes, int n_in,
                              void* d_out, int out_size) {
    const float* x    = (const float*)d_in[0];
    const float* st   = (const float*)d_in[1];
    const float* E    = (const float*)d_in[2];
    const float* mask = (const float*)d_in[3];
    const float* gW   = (const float*)d_in[4];
    const float* gb   = (const float*)d_in[5];
    const float* uW   = (const float*)d_in[6];
    const float* ub   = (const float*)d_in[7];
    const int*   normp = (const int*)d_in[8];
    float* outp = (float*)d_out;

    void *pX0, *pY1, *pY2, *pXth, *pYth;
    cudaGetSymbolAddress(&pX0, g_X0);
    cudaGetSymbolAddress(&pY1, g_Y1);
    cudaGetSymbolAddress(&pY2, g_Y2);
    cudaGetSymbolAddress(&pXth, g_Xth);
    cudaGetSymbolAddress(&pYth, g_Yth);

    const int smem_mma = 2 * STG;                                 // 40960
    cudaFuncSetAttribute(mma_gemm<0>, cudaFuncAttributeMaxDynamicSharedMemorySize, smem_mma);
    cudaFuncSetAttribute(mma_gemm<1>, cudaFuncAttributeMaxDynamicSharedMemorySize, smem_mma);

    const int smem_g = (Bb * KC + TKI * OG) * 4;                  // 67584
    const int smem_u = (Bb * KC + TKI * OU) * 4;                  // 59136
    cudaFuncSetAttribute(proj_kernel<OG, true>, cudaFuncAttributeMaxDynamicSharedMemorySize, smem_g);
    cudaFuncSetAttribute(proj_kernel<OU, false>, cudaFuncAttributeMaxDynamicSharedMemorySize, smem_u);

    dim3 gg(BC / NT, Nn / MT);                   // (33, 16)
    dim3 pg(Nn / 32, Bb);                        // (64, 64)
    dim3 tg(BC / 32, Nn / 32);                   // (132, 64)

    supports_kernel<<<Nn, 256>>>(E, mask, normp);

    // gate GCN
    pack_kernel<false><<<pg, 256>>>(x, st);
    mma_gemm<0><<<gg, 256, smem_mma>>>((const __half*)pXth, nullptr, (float*)pY1);
    tsplit_kernel<<<tg, dim3(32, 8)>>>();
    mma_gemm<1><<<gg, 256, smem_mma>>>((const __half*)pYth, (const float*)pX0, (float*)pY2);
    proj_kernel<OG, true><<<Nn, 256, smem_g>>>(E, gW, gb, nullptr, nullptr);

    // candidate GCN + GRU combine
    pack_kernel<true><<<pg, 256>>>(x, st);
    mma_gemm<0><<<gg, 256, smem_mma>>>((const __half*)pXth, nullptr, (float*)pY1);
    tsplit_kernel<<<tg, dim3(32, 8)>>>();
    mma_gemm<1><<<gg, 256, smem_mma>>>((const __half*)pYth, (const float*)pX0, (float*)pY2);
    proj_kernel<OU, false><<<Nn, 256, smem_u>>>(E, uW, ub, st, outp);
}